// round 12
// baseline (speedup 1.0000x reference)
#include <cuda_runtime.h>
#include <cuda_fp16.h>
#include <math.h>
#include <stdint.h>

#define B_  32
#define H_  56
#define W_  56
#define C_  192
#define D_  64
#define M_  8
#define HW_ 3136
#define N_  (B_*HW_)

// ---------------- device scratch (no allocations allowed) ----------------
__device__ __half g_pf[(size_t)N_ * 64];            // [n][64] half
__device__ __half g_xp[(size_t)B_ * D_ * HW_];      // [b][d][hw] half
__device__ float  g_logits[(size_t)M_ * B_ * HW_];  // [m][b][hw]
__device__ float  g_stats[M_ * B_ * 2];             // per (m,b): max(=0), 1/sum
__device__ float  g_part[B_ * 8 * 64];              // partial mwf
__device__ __half g_convwh[(size_t)B_ * 36864];     // [b][tap*64+oc][ic] half

__device__ __forceinline__ float qgelu(float v) {
    return v / (1.f + __expf(-1.702f * v));
}
__device__ __forceinline__ float tf32r(float v) {
    float r; asm("cvt.rna.tf32.f32 %0, %1;" : "=f"(r) : "f"(v)); return r;
}
// mma.sync m16n8k8 tf32
__device__ __forceinline__ void mma8(float* c, float a0, float a1, float a2, float a3,
                                     float b0, float b1) {
    asm volatile(
        "mma.sync.aligned.m16n8k8.row.col.f32.tf32.tf32.f32 "
        "{%0,%1,%2,%3}, {%4,%5,%6,%7}, {%8,%9}, {%0,%1,%2,%3};"
        : "+f"(c[0]), "+f"(c[1]), "+f"(c[2]), "+f"(c[3])
        : "r"(__float_as_uint(a0)), "r"(__float_as_uint(a1)),
          "r"(__float_as_uint(a2)), "r"(__float_as_uint(a3)),
          "r"(__float_as_uint(b0)), "r"(__float_as_uint(b1)));
}
// mma.sync m16n8k16 f16 inputs, f32 accum
__device__ __forceinline__ void mma16h(float* c, uint32_t a0, uint32_t a1,
                                       uint32_t a2, uint32_t a3,
                                       uint32_t b0, uint32_t b1) {
    asm volatile(
        "mma.sync.aligned.m16n8k16.row.col.f32.f16.f16.f32 "
        "{%0,%1,%2,%3}, {%4,%5,%6,%7}, {%8,%9}, {%0,%1,%2,%3};"
        : "+f"(c[0]), "+f"(c[1]), "+f"(c[2]), "+f"(c[3])
        : "r"(a0), "r"(a1), "r"(a2), "r"(a3), "r"(b0), "r"(b1));
}

// ============================================================================
// K1: main GEMM (tf32 mma) -> relu/gelu; pf = hs@W2^T (tf32 mma);
//     logits = pf @ mask^T (tf32 mma). 256 threads, 2 blocks/SM.
// ============================================================================
__global__ __launch_bounds__(256, 2) void k1(
    const float* __restrict__ x, const float* __restrict__ W1, const float* __restrict__ b1,
    const float* __restrict__ W2, const float* __restrict__ b2, const float* __restrict__ mtok,
    const float* __restrict__ Wd, const float* __restrict__ bd)
{
    extern __shared__ float sm[];
    float* Ah = sm, *Bh = sm + 4608;
    float* hs = sm;
    __half* xsh = (__half*)(sm + 8704);
    float* W2s = sm + 12928;
    __shared__ float mt_s[M_ * 68];

    const int tid   = threadIdx.x;
    const int warp  = tid >> 5, lane = tid & 31;
    const int gID   = lane >> 2, tig = lane & 3;
    const int b     = blockIdx.y;
    const int hw0   = blockIdx.x * 128;
    const int P     = min(128, HW_ - hw0);

    for (int i = tid; i < 512; i += 256) {
        int m = i >> 6, k = i & 63;
        mt_s[m * 68 + k] = tf32r(mtok[m * 64 + k]);
    }

    float c[16][4];
    #pragma unroll
    for (int nt = 0; nt < 16; nt++)
        #pragma unroll
        for (int j = 0; j < 4; j++) c[nt][j] = 0.f;

    const float* xb = x + (size_t)(b * HW_ + hw0) * C_;

    for (int ch = 0; ch < 6; ch++) {
        const int k0 = ch * 32;
        __syncthreads();
        for (int i = tid; i < 1024; i += 256) {
            int r = i >> 3, q = i & 7;
            float4 v = make_float4(0.f, 0.f, 0.f, 0.f);
            if (r < P) v = *(const float4*)(xb + (size_t)r * C_ + k0 + q * 4);
            v.x = tf32r(v.x); v.y = tf32r(v.y); v.z = tf32r(v.z); v.w = tf32r(v.w);
            *(float4*)(Ah + r * 36 + q * 4) = v;
        }
        for (int i = tid; i < 1024; i += 256) {
            int n = i >> 3, q = i & 7;
            const float* src = (n < 64) ? (W1 + n * C_) : (Wd + (n - 64) * C_);
            float4 v = *(const float4*)(src + k0 + q * 4);
            v.x = tf32r(v.x); v.y = tf32r(v.y); v.z = tf32r(v.z); v.w = tf32r(v.w);
            *(float4*)(Bh + n * 36 + q * 4) = v;
        }
        __syncthreads();

        const int arow0 = warp * 16 + gID;
        #pragma unroll
        for (int ks = 0; ks < 4; ks++) {
            const int kk = ks * 8;
            float a0 = Ah[arow0 * 36 + kk + tig];
            float a1 = Ah[(arow0 + 8) * 36 + kk + tig];
            float a2 = Ah[arow0 * 36 + kk + tig + 4];
            float a3 = Ah[(arow0 + 8) * 36 + kk + tig + 4];
            #pragma unroll
            for (int nt = 0; nt < 16; nt++) {
                const int bn = nt * 8 + gID;
                float b0 = Bh[bn * 36 + kk + tig];
                float b1 = Bh[bn * 36 + kk + tig + 4];
                mma8(c[nt], a0, a1, a2, a3, b0, b1);
            }
        }
    }
    __syncthreads();   // staging dead; overlay hs/xsh/W2s

    // epilogue: cols 0-63 relu -> hs (tf32-rounded); 64-127 qgelu -> xsh half
    {
        const int p0 = warp * 16 + gID, p1 = p0 + 8;
        #pragma unroll
        for (int nt = 0; nt < 16; nt++) {
            const int n = nt * 8 + tig * 2;
            if (nt < 8) {
                float bia = b1[n], bib = b1[n + 1];
                hs[p0 * 68 + n]     = tf32r(fmaxf(c[nt][0] + bia, 0.f));
                hs[p0 * 68 + n + 1] = tf32r(fmaxf(c[nt][1] + bib, 0.f));
                hs[p1 * 68 + n]     = tf32r(fmaxf(c[nt][2] + bia, 0.f));
                hs[p1 * 68 + n + 1] = tf32r(fmaxf(c[nt][3] + bib, 0.f));
            } else {
                const int d = n - 64;
                float bia = bd[d], bib = bd[d + 1];
                xsh[d * 132 + p0]       = __float2half_rn(qgelu(c[nt][0] + bia));
                xsh[(d + 1) * 132 + p0] = __float2half_rn(qgelu(c[nt][1] + bib));
                xsh[d * 132 + p1]       = __float2half_rn(qgelu(c[nt][2] + bia));
                xsh[(d + 1) * 132 + p1] = __float2half_rn(qgelu(c[nt][3] + bib));
            }
        }
    }
    // stage W2s tf32 [o][k] stride 68
    for (int i = tid; i < 4096; i += 256) {
        int o = i >> 6, kk = i & 63;
        W2s[o * 68 + kk] = tf32r(W2[i]);
    }
    __syncthreads();

    // coalesced g_xp write (half2)
    {
        __half2* xpb = (__half2*)(g_xp + (size_t)b * D_ * HW_ + hw0);
        for (int i = tid; i < 4096; i += 256) {
            int d = i >> 6, pp = i & 63;
            int p = pp * 2;
            if (p < P) {
                __half2 v = __halves2half2(xsh[d * 132 + p], xsh[d * 132 + p + 1]);
                xpb[(size_t)d * (HW_ / 2) + pp] = v;
            }
        }
    }

    // pf = hs @ W2^T via tf32 mma: M=128, N=64, K=64
    float cc[8][4];
    #pragma unroll
    for (int nt = 0; nt < 8; nt++)
        #pragma unroll
        for (int j = 0; j < 4; j++) cc[nt][j] = 0.f;
    {
        const int arow0 = warp * 16 + gID;
        #pragma unroll
        for (int ks = 0; ks < 8; ks++) {
            const int kk = ks * 8;
            float a0 = hs[arow0 * 68 + kk + tig];
            float a1 = hs[(arow0 + 8) * 68 + kk + tig];
            float a2 = hs[arow0 * 68 + kk + tig + 4];
            float a3 = hs[(arow0 + 8) * 68 + kk + tig + 4];
            #pragma unroll
            for (int nt = 0; nt < 8; nt++) {
                const int bn = nt * 8 + gID;
                float b0 = W2s[bn * 68 + kk + tig];
                float b1 = W2s[bn * 68 + kk + tig + 4];
                mma8(cc[nt], a0, a1, a2, a3, b0, b1);
            }
        }
    }
    __syncthreads();   // all pf reads of hs done before overwrite

    // write pf: hs (tf32-rounded, for logits mma) + g_pf (half2)
    {
        const int p0 = warp * 16 + gID, p1 = p0 + 8;
        #pragma unroll
        for (int nt = 0; nt < 8; nt++) {
            const int n = nt * 8 + tig * 2;
            float bia = b2[n], bib = b2[n + 1];
            float v00 = cc[nt][0] + bia, v01 = cc[nt][1] + bib;
            float v10 = cc[nt][2] + bia, v11 = cc[nt][3] + bib;
            hs[p0 * 68 + n]     = tf32r(v00);
            hs[p0 * 68 + n + 1] = tf32r(v01);
            hs[p1 * 68 + n]     = tf32r(v10);
            hs[p1 * 68 + n + 1] = tf32r(v11);
            if (p0 < P)
                *(__half2*)(g_pf + (size_t)(b * HW_ + hw0 + p0) * 64 + n) =
                    __floats2half2_rn(v00, v01);
            if (p1 < P)
                *(__half2*)(g_pf + (size_t)(b * HW_ + hw0 + p1) * 64 + n) =
                    __floats2half2_rn(v10, v11);
        }
    }
    __syncthreads();

    // logits = pf @ mask^T via tf32 mma: M=128, N=8, K=64
    {
        float cl[4] = {0.f, 0.f, 0.f, 0.f};
        const int arow0 = warp * 16 + gID;
        #pragma unroll
        for (int ks = 0; ks < 8; ks++) {
            const int kk = ks * 8;
            float a0 = hs[arow0 * 68 + kk + tig];
            float a1 = hs[(arow0 + 8) * 68 + kk + tig];
            float a2 = hs[arow0 * 68 + kk + tig + 4];
            float a3 = hs[(arow0 + 8) * 68 + kk + tig + 4];
            float b0 = mt_s[gID * 68 + kk + tig];
            float b1 = mt_s[gID * 68 + kk + tig + 4];
            mma8(cl, a0, a1, a2, a3, b0, b1);
        }
        const int p0 = warp * 16 + gID, p1 = p0 + 8;
        const int m0 = tig * 2, m1 = tig * 2 + 1;
        if (p0 < P) {
            g_logits[(size_t)(m0 * B_ + b) * HW_ + hw0 + p0] = cl[0];
            g_logits[(size_t)(m1 * B_ + b) * HW_ + hw0 + p0] = cl[1];
        }
        if (p1 < P) {
            g_logits[(size_t)(m0 * B_ + b) * HW_ + hw0 + p1] = cl[2];
            g_logits[(size_t)(m1 * B_ + b) * HW_ + hw0 + p1] = cl[3];
        }
    }
}

// ============================================================================
// K2: per-(m,b) softmax SUM over 3136 positions (|logits|~0.1 -> no max needed)
// ============================================================================
__global__ __launch_bounds__(128) void k2()
{
    int row = blockIdx.x;
    const float* l = g_logits + (size_t)row * HW_;
    __shared__ float red[128];
    int tid = threadIdx.x;

    float sum = 0.f;
    for (int p = tid; p < HW_; p += 128) sum += __expf(l[p]);
    red[tid] = sum; __syncthreads();
    for (int s = 64; s > 0; s >>= 1) {
        if (tid < s) red[tid] += red[tid + s];
        __syncthreads();
    }
    if (tid == 0) { g_stats[row * 2] = 0.f; g_stats[row * 2 + 1] = 1.f / red[0]; }
}

// ============================================================================
// K3a: partial mwf over 392-position chunks. grid (8, 32). pf in half.
// ============================================================================
__global__ __launch_bounds__(256) void k3a()
{
    const int chunk = blockIdx.x, b = blockIdx.y;
    const int tid = threadIdx.x;
    const int p0 = chunk * 392;
    __shared__ float ms[392];
    __shared__ float izs[M_];
    __shared__ float red[4][64];

    if (tid < M_) izs[tid] = g_stats[(tid * B_ + b) * 2 + 1];
    __syncthreads();

    for (int p = tid; p < 392; p += 256) {
        float s = 0.f;
        #pragma unroll
        for (int m = 0; m < M_; m++)
            s += __expf(g_logits[(size_t)(m * B_ + b) * HW_ + p0 + p]) * izs[m];
        ms[p] = s;
    }
    __syncthreads();

    int k = tid & 63, g = tid >> 6;
    float acc = 0.f;
    const __half* pfb = g_pf + (size_t)(b * HW_ + p0) * 64;
    for (int p = g; p < 392; p += 4)
        acc = fmaf(ms[p], __half2float(pfb[(size_t)p * 64 + k]), acc);
    red[g][k] = acc;
    __syncthreads();
    if (g == 0)
        g_part[(b * 8 + chunk) * 64 + k] = red[0][k] + red[1][k] + red[2][k] + red[3][k];
}

// ============================================================================
// K4: reduce g_part -> mwf; conv_w -> g_convwh in k5 layout [b][tap*64+oc][ic]
// grid (144, 2): blockIdx.y splits the batch loop (16 each) for latency hiding
// ============================================================================
__global__ __launch_bounds__(256) void k4(const float* __restrict__ Wh,
                                          const float* __restrict__ bh)
{
    __shared__ float ms[2048];
    int tid = threadIdx.x;
    for (int i = tid; i < 2048; i += 256) {
        int bb = i >> 6, k = i & 63;
        float acc = 0.f;
        #pragma unroll
        for (int cch = 0; cch < 8; cch++) acc += g_part[(bb * 8 + cch) * 64 + k];
        ms[i] = acc;
    }
    __syncthreads();

    int i = blockIdx.x * 256 + tid;
    int tap = i >> 12, oc = (i >> 6) & 63, ic = i & 63;
    int o = oc * 576 + ic * 9 + tap;
    float4 wv[16];
    const float4* wr = (const float4*)(Wh + (size_t)o * 64);
    #pragma unroll
    for (int q = 0; q < 16; q++) wv[q] = wr[q];
    const float* wf = (const float*)wv;
    float bias = bh[o];

    const int b0 = blockIdx.y * 16;
    for (int b = b0; b < b0 + 16; b++) {
        float acc = bias;
        const float* mb = ms + b * 64;
        #pragma unroll
        for (int kk = 0; kk < 64; kk++) acc = fmaf(mb[kk], wf[kk], acc);
        g_convwh[(size_t)b * 36864 + i] = __float2half_rn(acc);
    }
}

// ============================================================================
// K5: conv (f16 m16n8k16 mma) + quickGELU + up-proj (f16 mma) + residual.
// tile 8 rows x 32 cols = 256 positions (m = c*8+r), 256 threads, 2 blocks/SM.
// ============================================================================
__global__ __launch_bounds__(256, 2) void k5(const float* __restrict__ x,
                                             const float* __restrict__ Wu,
                                             const float* __restrict__ bu,
                                             float* __restrict__ out)
{
    extern __shared__ float sm[];
    __half* hbase = (__half*)sm;
    __half* hin_h = hbase;             // [340 spatial][20] halves (13600 B)
    __half* Bw_h  = hbase + 6800;      // [576][24] halves (27648 B)
    __half* gbuf  = hbase;             // overlay: [256 m][72] halves (36864 B)
    __half* wuh   = hbase + 18432;     // overlay: [192 n][72] halves (27648 B)
    __shared__ float bus[C_];

    const int tid  = threadIdx.x;
    const int warp = tid >> 5, lane = tid & 31;
    const int gID  = lane >> 2, tig = lane & 3;
    const int b    = blockIdx.y;
    const int t    = blockIdx.x;          // 0..13
    const int row0 = (t % 7) * 8;
    const int col0 = (t / 7) * 24;        // {0, 24}; cols overlap (benign dup)

    for (int i = tid; i < C_; i += 256) bus[i] = bu[i];

    float c[2][8][4];
    #pragma unroll
    for (int mtl = 0; mtl < 2; mtl++)
        #pragma unroll
        for (int nt = 0; nt < 8; nt++)
            #pragma unroll
            for (int j = 0; j < 4; j++) c[mtl][nt][j] = 0.f;

    for (int ci = 0; ci < 4; ci++) {
        __syncthreads();
        // stage halo input [10][34] x 16 ic (half2 per ic-pair)
        for (int i = tid; i < 2720; i += 256) {
            int s = i >> 3, jc = i & 7;
            int hr = s / 34, hc = s % 34;
            int gy = row0 - 1 + hr, gx = col0 - 1 + hc;
            __half2 v = __halves2half2(__float2half(0.f), __float2half(0.f));
            if (gy >= 0 && gy < H_ && gx >= 0 && gx < W_) {
                size_t base = (size_t)(b * D_ + ci * 16 + 2 * jc) * HW_ + gy * W_ + gx;
                v = __halves2half2(g_xp[base], g_xp[base + HW_]);
            }
            *(__half2*)(hin_h + s * 20 + 2 * jc) = v;
        }
        // stage weights: Bw_h[rest][ic_local] from g_convwh[b][rest][ci*16+ic_local]
        for (int i = tid; i < 4608; i += 256) {
            int rest = i >> 3, jc = i & 7;
            *(__half2*)(Bw_h + rest * 24 + 2 * jc) =
                *(const __half2*)(g_convwh + (size_t)b * 36864 + rest * 64 + ci * 16 + 2 * jc);
        }
        __syncthreads();

        #pragma unroll
        for (int tap = 0; tap < 9; tap++) {
            const int dy = tap / 3, dx = tap % 3;
            uint32_t a[2][4];
            #pragma unroll
            for (int mtl = 0; mtl < 2; mtl++) {
                const __half* ap = hin_h +
                    ((gID + dy) * 34 + 4 * warp + 2 * mtl + dx) * 20 + 2 * tig;
                a[mtl][0] = *(const uint32_t*)(ap);
                a[mtl][1] = *(const uint32_t*)(ap + 20);   // m+8 (next spatial col)
                a[mtl][2] = *(const uint32_t*)(ap + 8);    // k+8
                a[mtl][3] = *(const uint32_t*)(ap + 28);
            }
            #pragma unroll
            for (int nt = 0; nt < 8; nt++) {
                const __half* bp = Bw_h + (tap * 64 + nt * 8 + gID) * 24 + 2 * tig;
                uint32_t b0 = *(const uint32_t*)(bp);
                uint32_t b1 = *(const uint32_t*)(bp + 8);
                mma16h(c[0][nt], a[0][0], a[0][1], a[0][2], a[0][3], b0, b1);
                mma16h(c[1][nt], a[1][0], a[1][1], a[1][2], a[1][3], b0, b1);
            }
        }
    }
    __syncthreads();   // conv done; overlay gbuf/wuh

    // quickGELU -> gbuf half2, stride 72
    #pragma unroll
    for (int mtl = 0; mtl < 2; mtl++) {
        int m0 = (2 * warp + mtl) * 16 + gID;
        #pragma unroll
        for (int nt = 0; nt < 8; nt++) {
            int oc = nt * 8 + tig * 2;
            *(__half2*)(gbuf + m0 * 72 + oc) =
                __floats2half2_rn(qgelu(c[mtl][nt][0]), qgelu(c[mtl][nt][1]));
            *(__half2*)(gbuf + (m0 + 8) * 72 + oc) =
                __floats2half2_rn(qgelu(c[mtl][nt][2]), qgelu(c[mtl][nt][3]));
        }
    }
    // stage Wu as half: wuh[n][k]
    for (int i = tid; i < 12288; i += 256) {
        int n = i >> 6, k = i & 63;
        wuh[n * 72 + k] = __float2half_rn(Wu[i]);
    }
    __syncthreads();

    // up-proj: D[256 pos][192 ch] = gbuf @ wuh^T via f16 mma, 3 passes of 64 ch
    for (int pass = 0; pass < 3; pass++) {
        float cc[2][8][4];
        #pragma unroll
        for (int mtl = 0; mtl < 2; mtl++)
            #pragma unroll
            for (int nt = 0; nt < 8; nt++)
                #pragma unroll
                for (int j = 0; j < 4; j++) cc[mtl][nt][j] = 0.f;

        #pragma unroll
        for (int ks = 0; ks < 4; ks++) {
            const int k0 = ks * 16;
            uint32_t a[2][4];
            #pragma unroll
            for (int mtl = 0; mtl < 2; mtl++) {
                int r0 = (warp * 2 + mtl) * 16 + gID;
                const __half* g0 = gbuf + r0 * 72 + k0 + tig * 2;
                a[mtl][0] = *(const uint32_t*)(g0);
                a[mtl][1] = *(const uint32_t*)(g0 + 8 * 72);
                a[mtl][2] = *(const uint32_t*)(g0 + 8);
                a[mtl][3] = *(const uint32_t*)(g0 + 8 * 72 + 8);
            }
            #pragma unroll
            for (int nt = 0; nt < 8; nt++) {
                const __half* w0 = wuh + (pass * 64 + nt * 8 + gID) * 72 + k0 + tig * 2;
                uint32_t b0 = *(const uint32_t*)(w0);
                uint32_t b1 = *(const uint32_t*)(w0 + 8);
                mma16h(cc[0][nt], a[0][0], a[0][1], a[0][2], a[0][3], b0, b1);
                mma16h(cc[1][nt], a[1][0], a[1][1], a[1][2], a[1][3], b0, b1);
            }
        }
        // epilogue: residual + bias, direct float2 stores
        #pragma unroll
        for (int mtl = 0; mtl < 2; mtl++) {
            #pragma unroll
            for (int hf = 0; hf < 2; hf++) {
                int m = (warp * 2 + mtl) * 16 + gID + hf * 8;
                int gy = row0 + (m & 7), gx = col0 + (m >> 3);
                size_t n = (size_t)b * HW_ + gy * W_ + gx;
                const float* xr = x + n * C_;
                float* orr = out + n * C_;
                #pragma unroll
                for (int nt = 0; nt < 8; nt++) {
                    int chn = pass * 64 + nt * 8 + tig * 2;
                    float2 xv = *(const float2*)(xr + chn);
                    float v0 = cc[mtl][nt][hf * 2 + 0] + bus[chn]     + xv.x;
                    float v1 = cc[mtl][nt][hf * 2 + 1] + bus[chn + 1] + xv.y;
                    *(float2*)(orr + chn) = make_float2(v0, v1);
                }
            }
        }
    }
}

// ============================================================================
extern "C" void kernel_launch(void* const* d_in, const int* in_sizes, int n_in,
                              void* d_out, int out_size)
{
    const float* x  = (const float*)d_in[0];
    const float* W1 = (const float*)d_in[1];
    const float* b1 = (const float*)d_in[2];
    const float* W2 = (const float*)d_in[3];
    const float* b2 = (const float*)d_in[4];
    const float* mt = (const float*)d_in[5];
    const float* Wh = (const float*)d_in[6];
    const float* bh = (const float*)d_in[7];
    const float* Wd = (const float*)d_in[8];
    const float* bd = (const float*)d_in[9];
    const float* Wu = (const float*)d_in[10];
    const float* bu = (const float*)d_in[11];
    float* out = (float*)d_out;

    cudaFuncSetAttribute(k1, cudaFuncAttributeMaxDynamicSharedMemorySize, 69120);
    cudaFuncSetAttribute(k5, cudaFuncAttributeMaxDynamicSharedMemorySize, 64512);

    k1<<<dim3(25, 32), 256, 69120>>>(x, W1, b1, W2, b2, mt, Wd, bd);
    k2<<<256, 128>>>();
    k3a<<<dim3(8, 32), 256>>>();
    k4<<<dim3(144, 2), 256>>>(Wh, bh);
    k5<<<dim3(14, 32), 256, 64512>>>(x, Wu, bu, out);
}

// round 13
// speedup vs baseline: 1.3276x; 1.3276x over previous
#include <cuda_runtime.h>
#include <cuda_fp16.h>
#include <math.h>
#include <stdint.h>

#define B_  32
#define H_  56
#define W_  56
#define C_  192
#define D_  64
#define M_  8
#define HW_ 3136
#define N_  (B_*HW_)

// ---------------- device scratch (no allocations allowed) ----------------
__device__ float  g_pf[(size_t)N_ * 64];            // [n][64]
__device__ __half g_xp[(size_t)B_ * D_ * HW_];      // [b][d][hw] half
__device__ float  g_logits[(size_t)M_ * B_ * HW_];  // [m][b][hw]
__device__ float  g_stats[M_ * B_ * 2];             // per (m,b): max(=0), 1/sum
__device__ float  g_part[B_ * 8 * 64];              // partial mwf
__device__ float  g_convw[(size_t)B_ * D_ * D_ * 9];// [b][oc][ic][3][3]

__device__ __forceinline__ float qgelu(float v) {
    return v / (1.f + __expf(-1.702f * v));
}
__device__ __forceinline__ float tf32r(float v) {
    float r; asm("cvt.rna.tf32.f32 %0, %1;" : "=f"(r) : "f"(v)); return r;
}
// mma.sync m16n8k8 tf32
__device__ __forceinline__ void mma8(float* c, float a0, float a1, float a2, float a3,
                                     float b0, float b1) {
    asm volatile(
        "mma.sync.aligned.m16n8k8.row.col.f32.tf32.tf32.f32 "
        "{%0,%1,%2,%3}, {%4,%5,%6,%7}, {%8,%9}, {%0,%1,%2,%3};"
        : "+f"(c[0]), "+f"(c[1]), "+f"(c[2]), "+f"(c[3])
        : "r"(__float_as_uint(a0)), "r"(__float_as_uint(a1)),
          "r"(__float_as_uint(a2)), "r"(__float_as_uint(a3)),
          "r"(__float_as_uint(b0)), "r"(__float_as_uint(b1)));
}
// mma.sync m16n8k16 f16 inputs, f32 accum
__device__ __forceinline__ void mma16h(float* c, uint32_t a0, uint32_t a1,
                                       uint32_t a2, uint32_t a3,
                                       uint32_t b0, uint32_t b1) {
    asm volatile(
        "mma.sync.aligned.m16n8k16.row.col.f32.f16.f16.f32 "
        "{%0,%1,%2,%3}, {%4,%5,%6,%7}, {%8,%9}, {%0,%1,%2,%3};"
        : "+f"(c[0]), "+f"(c[1]), "+f"(c[2]), "+f"(c[3])
        : "r"(a0), "r"(a1), "r"(a2), "r"(a3), "r"(b0), "r"(b1));
}

// ============================================================================
// K1: main GEMM (tf32 mma) -> relu/gelu; pf = hs@W2^T (tf32 mma);
//     logits = pf @ mask^T (tf32 mma). 256 threads, 2 blocks/SM.
// ============================================================================
__global__ __launch_bounds__(256, 2) void k1(
    const float* __restrict__ x, const float* __restrict__ W1, const float* __restrict__ b1,
    const float* __restrict__ W2, const float* __restrict__ b2, const float* __restrict__ mtok,
    const float* __restrict__ Wd, const float* __restrict__ bd)
{
    extern __shared__ float sm[];
    float* Ah = sm, *Bh = sm + 4608;
    float* hs = sm;
    __half* xsh = (__half*)(sm + 8704);
    float* W2s = sm + 12928;
    __shared__ float mt_s[M_ * 68];

    const int tid   = threadIdx.x;
    const int warp  = tid >> 5, lane = tid & 31;
    const int gID   = lane >> 2, tig = lane & 3;
    const int b     = blockIdx.y;
    const int hw0   = blockIdx.x * 128;
    const int P     = min(128, HW_ - hw0);

    for (int i = tid; i < 512; i += 256) {
        int m = i >> 6, k = i & 63;
        mt_s[m * 68 + k] = tf32r(mtok[m * 64 + k]);
    }

    float c[16][4];
    #pragma unroll
    for (int nt = 0; nt < 16; nt++)
        #pragma unroll
        for (int j = 0; j < 4; j++) c[nt][j] = 0.f;

    const float* xb = x + (size_t)(b * HW_ + hw0) * C_;

    for (int ch = 0; ch < 6; ch++) {
        const int k0 = ch * 32;
        __syncthreads();
        for (int i = tid; i < 1024; i += 256) {
            int r = i >> 3, q = i & 7;
            float4 v = make_float4(0.f, 0.f, 0.f, 0.f);
            if (r < P) v = *(const float4*)(xb + (size_t)r * C_ + k0 + q * 4);
            v.x = tf32r(v.x); v.y = tf32r(v.y); v.z = tf32r(v.z); v.w = tf32r(v.w);
            *(float4*)(Ah + r * 36 + q * 4) = v;
        }
        for (int i = tid; i < 1024; i += 256) {
            int n = i >> 3, q = i & 7;
            const float* src = (n < 64) ? (W1 + n * C_) : (Wd + (n - 64) * C_);
            float4 v = *(const float4*)(src + k0 + q * 4);
            v.x = tf32r(v.x); v.y = tf32r(v.y); v.z = tf32r(v.z); v.w = tf32r(v.w);
            *(float4*)(Bh + n * 36 + q * 4) = v;
        }
        __syncthreads();

        const int arow0 = warp * 16 + gID;
        #pragma unroll
        for (int ks = 0; ks < 4; ks++) {
            const int kk = ks * 8;
            float a0 = Ah[arow0 * 36 + kk + tig];
            float a1 = Ah[(arow0 + 8) * 36 + kk + tig];
            float a2 = Ah[arow0 * 36 + kk + tig + 4];
            float a3 = Ah[(arow0 + 8) * 36 + kk + tig + 4];
            #pragma unroll
            for (int nt = 0; nt < 16; nt++) {
                const int bn = nt * 8 + gID;
                float b0 = Bh[bn * 36 + kk + tig];
                float b1 = Bh[bn * 36 + kk + tig + 4];
                mma8(c[nt], a0, a1, a2, a3, b0, b1);
            }
        }
    }
    __syncthreads();   // staging dead; overlay hs/xsh/W2s

    // epilogue: cols 0-63 relu -> hs (tf32-rounded); 64-127 qgelu -> xsh half
    {
        const int p0 = warp * 16 + gID, p1 = p0 + 8;
        #pragma unroll
        for (int nt = 0; nt < 16; nt++) {
            const int n = nt * 8 + tig * 2;
            if (nt < 8) {
                float bia = b1[n], bib = b1[n + 1];
                hs[p0 * 68 + n]     = tf32r(fmaxf(c[nt][0] + bia, 0.f));
                hs[p0 * 68 + n + 1] = tf32r(fmaxf(c[nt][1] + bib, 0.f));
                hs[p1 * 68 + n]     = tf32r(fmaxf(c[nt][2] + bia, 0.f));
                hs[p1 * 68 + n + 1] = tf32r(fmaxf(c[nt][3] + bib, 0.f));
            } else {
                const int d = n - 64;
                float bia = bd[d], bib = bd[d + 1];
                xsh[d * 132 + p0]       = __float2half_rn(qgelu(c[nt][0] + bia));
                xsh[(d + 1) * 132 + p0] = __float2half_rn(qgelu(c[nt][1] + bib));
                xsh[d * 132 + p1]       = __float2half_rn(qgelu(c[nt][2] + bia));
                xsh[(d + 1) * 132 + p1] = __float2half_rn(qgelu(c[nt][3] + bib));
            }
        }
    }
    // stage W2s tf32 [o][k] stride 68
    for (int i = tid; i < 4096; i += 256) {
        int o = i >> 6, kk = i & 63;
        W2s[o * 68 + kk] = tf32r(W2[i]);
    }
    __syncthreads();

    // coalesced g_xp write (half2)
    {
        __half2* xpb = (__half2*)(g_xp + (size_t)b * D_ * HW_ + hw0);
        for (int i = tid; i < 4096; i += 256) {
            int d = i >> 6, pp = i & 63;
            int p = pp * 2;
            if (p < P) {
                __half2 v = __halves2half2(xsh[d * 132 + p], xsh[d * 132 + p + 1]);
                xpb[(size_t)d * (HW_ / 2) + pp] = v;
            }
        }
    }

    // pf = hs @ W2^T via tf32 mma: M=128, N=64, K=64
    float cc[8][4];
    #pragma unroll
    for (int nt = 0; nt < 8; nt++)
        #pragma unroll
        for (int j = 0; j < 4; j++) cc[nt][j] = 0.f;
    {
        const int arow0 = warp * 16 + gID;
        #pragma unroll
        for (int ks = 0; ks < 8; ks++) {
            const int kk = ks * 8;
            float a0 = hs[arow0 * 68 + kk + tig];
            float a1 = hs[(arow0 + 8) * 68 + kk + tig];
            float a2 = hs[arow0 * 68 + kk + tig + 4];
            float a3 = hs[(arow0 + 8) * 68 + kk + tig + 4];
            #pragma unroll
            for (int nt = 0; nt < 8; nt++) {
                const int bn = nt * 8 + gID;
                float b0 = W2s[bn * 68 + kk + tig];
                float b1 = W2s[bn * 68 + kk + tig + 4];
                mma8(cc[nt], a0, a1, a2, a3, b0, b1);
            }
        }
    }
    __syncthreads();   // all pf reads of hs done before overwrite

    // write pf: hs (tf32-rounded, for logits mma) + g_pf (float2)
    {
        const int p0 = warp * 16 + gID, p1 = p0 + 8;
        #pragma unroll
        for (int nt = 0; nt < 8; nt++) {
            const int n = nt * 8 + tig * 2;
            float bia = b2[n], bib = b2[n + 1];
            float v00 = cc[nt][0] + bia, v01 = cc[nt][1] + bib;
            float v10 = cc[nt][2] + bia, v11 = cc[nt][3] + bib;
            hs[p0 * 68 + n]     = tf32r(v00);
            hs[p0 * 68 + n + 1] = tf32r(v01);
            hs[p1 * 68 + n]     = tf32r(v10);
            hs[p1 * 68 + n + 1] = tf32r(v11);
            if (p0 < P)
                *(float2*)(g_pf + (size_t)(b * HW_ + hw0 + p0) * 64 + n) = make_float2(v00, v01);
            if (p1 < P)
                *(float2*)(g_pf + (size_t)(b * HW_ + hw0 + p1) * 64 + n) = make_float2(v10, v11);
        }
    }
    __syncthreads();

    // logits = pf @ mask^T via tf32 mma: M=128, N=8, K=64
    {
        float cl[4] = {0.f, 0.f, 0.f, 0.f};
        const int arow0 = warp * 16 + gID;
        #pragma unroll
        for (int ks = 0; ks < 8; ks++) {
            const int kk = ks * 8;
            float a0 = hs[arow0 * 68 + kk + tig];
            float a1 = hs[(arow0 + 8) * 68 + kk + tig];
            float a2 = hs[arow0 * 68 + kk + tig + 4];
            float a3 = hs[(arow0 + 8) * 68 + kk + tig + 4];
            float b0 = mt_s[gID * 68 + kk + tig];
            float b1 = mt_s[gID * 68 + kk + tig + 4];
            mma8(cl, a0, a1, a2, a3, b0, b1);
        }
        const int p0 = warp * 16 + gID, p1 = p0 + 8;
        const int m0 = tig * 2, m1 = tig * 2 + 1;
        if (p0 < P) {
            g_logits[(size_t)(m0 * B_ + b) * HW_ + hw0 + p0] = cl[0];
            g_logits[(size_t)(m1 * B_ + b) * HW_ + hw0 + p0] = cl[1];
        }
        if (p1 < P) {
            g_logits[(size_t)(m0 * B_ + b) * HW_ + hw0 + p1] = cl[2];
            g_logits[(size_t)(m1 * B_ + b) * HW_ + hw0 + p1] = cl[3];
        }
    }
}

// ============================================================================
// K2: per-(m,b) softmax SUM over 3136 positions (|logits|~0.1 -> no max needed;
// writes max=0 so downstream interface is unchanged)
// ============================================================================
__global__ __launch_bounds__(128) void k2()
{
    int row = blockIdx.x;
    const float* l = g_logits + (size_t)row * HW_;
    __shared__ float red[128];
    int tid = threadIdx.x;

    float sum = 0.f;
    for (int p = tid; p < HW_; p += 128) sum += __expf(l[p]);
    red[tid] = sum; __syncthreads();
    for (int s = 64; s > 0; s >>= 1) {
        if (tid < s) red[tid] += red[tid + s];
        __syncthreads();
    }
    if (tid == 0) { g_stats[row * 2] = 0.f; g_stats[row * 2 + 1] = 1.f / red[0]; }
}

// ============================================================================
// K3a: partial mwf over 392-position chunks. grid (8, 32)
// ============================================================================
__global__ __launch_bounds__(256) void k3a()
{
    const int chunk = blockIdx.x, b = blockIdx.y;
    const int tid = threadIdx.x;
    const int p0 = chunk * 392;
    __shared__ float ms[392];
    __shared__ float izs[M_];
    __shared__ float red[4][64];

    if (tid < M_) izs[tid] = g_stats[(tid * B_ + b) * 2 + 1];
    __syncthreads();

    for (int p = tid; p < 392; p += 256) {
        float s = 0.f;
        #pragma unroll
        for (int m = 0; m < M_; m++)
            s += __expf(g_logits[(size_t)(m * B_ + b) * HW_ + p0 + p]) * izs[m];
        ms[p] = s;
    }
    __syncthreads();

    int k = tid & 63, g = tid >> 6;
    float acc = 0.f;
    const float* pfb = g_pf + (size_t)(b * HW_ + p0) * 64;
    for (int p = g; p < 392; p += 4)
        acc = fmaf(ms[p], pfb[(size_t)p * 64 + k], acc);
    red[g][k] = acc;
    __syncthreads();
    if (g == 0)
        g_part[(b * 8 + chunk) * 64 + k] = red[0][k] + red[1][k] + red[2][k] + red[3][k];
}

// ============================================================================
// K4: reduce g_part -> mwf (smem), then conv_w[b,o] = mwf[b].Wh[o] + bh[o]
// ============================================================================
__global__ __launch_bounds__(256) void k4(const float* __restrict__ Wh,
                                          const float* __restrict__ bh)
{
    __shared__ float ms[2048];
    int tid = threadIdx.x;
    for (int i = tid; i < 2048; i += 256) {
        int bb = i >> 6, k = i & 63;
        float acc = 0.f;
        #pragma unroll
        for (int cch = 0; cch < 8; cch++) acc += g_part[(bb * 8 + cch) * 64 + k];
        ms[i] = acc;
    }
    __syncthreads();

    int o = blockIdx.x * 256 + tid;
    float4 wv[16];
    const float4* wr = (const float4*)(Wh + (size_t)o * 64);
    #pragma unroll
    for (int q = 0; q < 16; q++) wv[q] = wr[q];
    const float* wf = (const float*)wv;
    float bias = bh[o];

    for (int b = 0; b < B_; b++) {
        float acc = bias;
        const float* mb = ms + b * 64;
        #pragma unroll
        for (int kk = 0; kk < 64; kk++) acc = fmaf(mb[kk], wf[kk], acc);
        g_convw[(size_t)b * 36864 + o] = acc;
    }
}

// ============================================================================
// K5: conv (f16 m16n8k16 mma) + quickGELU + up-proj (f16 mma) + residual.
// tile 8 rows x 32 cols = 256 positions (m = c*8+r), 256 threads, 2 blocks/SM.
// ============================================================================
__global__ __launch_bounds__(256, 2) void k5(const float* __restrict__ x,
                                             const float* __restrict__ Wu,
                                             const float* __restrict__ bu,
                                             float* __restrict__ out)
{
    extern __shared__ float sm[];
    __half* hbase = (__half*)sm;
    __half* hin_h = hbase;             // [340 spatial][20] halves (13600 B)
    __half* Bw_h  = hbase + 6800;      // [576][24] halves (27648 B)
    __half* gbuf  = hbase;             // overlay: [256 m][72] halves (36864 B)
    __half* wuh   = hbase + 18432;     // overlay: [192 n][72] halves (27648 B)
    __shared__ float bus[C_];

    const int tid  = threadIdx.x;
    const int warp = tid >> 5, lane = tid & 31;
    const int gID  = lane >> 2, tig = lane & 3;
    const int b    = blockIdx.y;
    const int t    = blockIdx.x;          // 0..13
    const int row0 = (t % 7) * 8;
    const int col0 = (t / 7) * 24;        // {0, 24}; cols overlap (benign dup)

    for (int i = tid; i < C_; i += 256) bus[i] = bu[i];

    float c[2][8][4];
    #pragma unroll
    for (int mtl = 0; mtl < 2; mtl++)
        #pragma unroll
        for (int nt = 0; nt < 8; nt++)
            #pragma unroll
            for (int j = 0; j < 4; j++) c[mtl][nt][j] = 0.f;

    for (int ci = 0; ci < 4; ci++) {
        __syncthreads();
        // stage halo input [10][34] x 16 ic (half2 per ic-pair)
        for (int i = tid; i < 2720; i += 256) {
            int s = i >> 3, jc = i & 7;
            int hr = s / 34, hc = s % 34;
            int gy = row0 - 1 + hr, gx = col0 - 1 + hc;
            __half2 v = __halves2half2(__float2half(0.f), __float2half(0.f));
            if (gy >= 0 && gy < H_ && gx >= 0 && gx < W_) {
                size_t base = (size_t)(b * D_ + ci * 16 + 2 * jc) * HW_ + gy * W_ + gx;
                v = __halves2half2(g_xp[base], g_xp[base + HW_]);
            }
            *(__half2*)(hin_h + s * 20 + 2 * jc) = v;
        }
        // stage weights Bw_h[(tap*64+oc)][ic] halves
        for (int i = tid; i < 9216; i += 256) {
            int ic = i & 15, rest = i >> 4;
            int oc = rest & 63, tap = rest >> 6;
            Bw_h[rest * 24 + ic] =
                __float2half_rn(g_convw[(size_t)b * 36864 + oc * 576 + (ci * 16 + ic) * 9 + tap]);
        }
        __syncthreads();

        #pragma unroll
        for (int tap = 0; tap < 9; tap++) {
            const int dy = tap / 3, dx = tap % 3;
            uint32_t a[2][4];
            #pragma unroll
            for (int mtl = 0; mtl < 2; mtl++) {
                const __half* ap = hin_h +
                    ((gID + dy) * 34 + 4 * warp + 2 * mtl + dx) * 20 + 2 * tig;
                a[mtl][0] = *(const uint32_t*)(ap);
                a[mtl][1] = *(const uint32_t*)(ap + 20);   // m+8 (next spatial col)
                a[mtl][2] = *(const uint32_t*)(ap + 8);    // k+8
                a[mtl][3] = *(const uint32_t*)(ap + 28);
            }
            #pragma unroll
            for (int nt = 0; nt < 8; nt++) {
                const __half* bp = Bw_h + (tap * 64 + nt * 8 + gID) * 24 + 2 * tig;
                uint32_t b0 = *(const uint32_t*)(bp);
                uint32_t b1 = *(const uint32_t*)(bp + 8);
                mma16h(c[0][nt], a[0][0], a[0][1], a[0][2], a[0][3], b0, b1);
                mma16h(c[1][nt], a[1][0], a[1][1], a[1][2], a[1][3], b0, b1);
            }
        }
    }
    __syncthreads();   // conv done; overlay gbuf/wuh

    // quickGELU -> gbuf half2, stride 72
    #pragma unroll
    for (int mtl = 0; mtl < 2; mtl++) {
        int m0 = (2 * warp + mtl) * 16 + gID;
        #pragma unroll
        for (int nt = 0; nt < 8; nt++) {
            int oc = nt * 8 + tig * 2;
            *(__half2*)(gbuf + m0 * 72 + oc) =
                __floats2half2_rn(qgelu(c[mtl][nt][0]), qgelu(c[mtl][nt][1]));
            *(__half2*)(gbuf + (m0 + 8) * 72 + oc) =
                __floats2half2_rn(qgelu(c[mtl][nt][2]), qgelu(c[mtl][nt][3]));
        }
    }
    // stage Wu as half: wuh[n][k]
    for (int i = tid; i < 12288; i += 256) {
        int n = i >> 6, k = i & 63;
        wuh[n * 72 + k] = __float2half_rn(Wu[i]);
    }
    __syncthreads();

    // up-proj: D[256 pos][192 ch] = gbuf @ wuh^T via f16 mma, 3 passes of 64 ch
    for (int pass = 0; pass < 3; pass++) {
        float cc[2][8][4];
        #pragma unroll
        for (int mtl = 0; mtl < 2; mtl++)
            #pragma unroll
            for (int nt = 0; nt < 8; nt++)
                #pragma unroll
                for (int j = 0; j < 4; j++) cc[mtl][nt][j] = 0.f;

        #pragma unroll
        for (int ks = 0; ks < 4; ks++) {
            const int k0 = ks * 16;
            uint32_t a[2][4];
            #pragma unroll
            for (int mtl = 0; mtl < 2; mtl++) {
                int r0 = (warp * 2 + mtl) * 16 + gID;
                const __half* g0 = gbuf + r0 * 72 + k0 + tig * 2;
                a[mtl][0] = *(const uint32_t*)(g0);
                a[mtl][1] = *(const uint32_t*)(g0 + 8 * 72);
                a[mtl][2] = *(const uint32_t*)(g0 + 8);
                a[mtl][3] = *(const uint32_t*)(g0 + 8 * 72 + 8);
            }
            #pragma unroll
            for (int nt = 0; nt < 8; nt++) {
                const __half* w0 = wuh + (pass * 64 + nt * 8 + gID) * 72 + k0 + tig * 2;
                uint32_t b0 = *(const uint32_t*)(w0);
                uint32_t b1 = *(const uint32_t*)(w0 + 8);
                mma16h(cc[0][nt], a[0][0], a[0][1], a[0][2], a[0][3], b0, b1);
                mma16h(cc[1][nt], a[1][0], a[1][1], a[1][2], a[1][3], b0, b1);
            }
        }
        // epilogue: residual + bias, direct float2 stores
        #pragma unroll
        for (int mtl = 0; mtl < 2; mtl++) {
            #pragma unroll
            for (int hf = 0; hf < 2; hf++) {
                int m = (warp * 2 + mtl) * 16 + gID + hf * 8;
                int gy = row0 + (m & 7), gx = col0 + (m >> 3);
                size_t n = (size_t)b * HW_ + gy * W_ + gx;
                const float* xr = x + n * C_;
                float* orr = out + n * C_;
                #pragma unroll
                for (int nt = 0; nt < 8; nt++) {
                    int chn = pass * 64 + nt * 8 + tig * 2;
                    float2 xv = *(const float2*)(xr + chn);
                    float v0 = cc[mtl][nt][hf * 2 + 0] + bus[chn]     + xv.x;
                    float v1 = cc[mtl][nt][hf * 2 + 1] + bus[chn + 1] + xv.y;
                    *(float2*)(orr + chn) = make_float2(v0, v1);
                }
            }
        }
    }
}

// ============================================================================
extern "C" void kernel_launch(void* const* d_in, const int* in_sizes, int n_in,
                              void* d_out, int out_size)
{
    const float* x  = (const float*)d_in[0];
    const float* W1 = (const float*)d_in[1];
    const float* b1 = (const float*)d_in[2];
    const float* W2 = (const float*)d_in[3];
    const float* b2 = (const float*)d_in[4];
    const float* mt = (const float*)d_in[5];
    const float* Wh = (const float*)d_in[6];
    const float* bh = (const float*)d_in[7];
    const float* Wd = (const float*)d_in[8];
    const float* bd = (const float*)d_in[9];
    const float* Wu = (const float*)d_in[10];
    const float* bu = (const float*)d_in[11];
    float* out = (float*)d_out;

    cudaFuncSetAttribute(k1, cudaFuncAttributeMaxDynamicSharedMemorySize, 69120);
    cudaFuncSetAttribute(k5, cudaFuncAttributeMaxDynamicSharedMemorySize, 64512);

    k1<<<dim3(25, 32), 256, 69120>>>(x, W1, b1, W2, b2, mt, Wd, bd);
    k2<<<256, 128>>>();
    k3a<<<dim3(8, 32), 256>>>();
    k4<<<144, 256>>>(Wh, bh);
    k5<<<dim3(14, 32), 256, 64512>>>(x, Wu, bu, out);
}

// round 14
// speedup vs baseline: 1.5302x; 1.1526x over previous
#include <cuda_runtime.h>
#include <cuda_fp16.h>
#include <math.h>
#include <stdint.h>

#define B_  32
#define H_  56
#define W_  56
#define C_  192
#define D_  64
#define M_  8
#define HW_ 3136
#define N_  (B_*HW_)

// ---------------- device scratch (no allocations allowed) ----------------
__device__ float  g_pf[(size_t)N_ * 64];            // [n][64]
__device__ __half g_xp[(size_t)B_ * D_ * HW_];      // [b][d][hw] half
__device__ float  g_logits[(size_t)M_ * B_ * HW_];  // [m][b][hw]
__device__ float  g_sums[M_ * B_];                  // per (m,b): sum of exp
__device__ float  g_part[B_ * 8 * 64];              // partial mwf
__device__ float  g_convw[(size_t)B_ * D_ * D_ * 9];// [b][oc][ic][3][3]

__device__ __forceinline__ float qgelu(float v) {
    return v / (1.f + __expf(-1.702f * v));
}
__device__ __forceinline__ float tf32r(float v) {
    float r; asm("cvt.rna.tf32.f32 %0, %1;" : "=f"(r) : "f"(v)); return r;
}
// mma.sync m16n8k8 tf32
__device__ __forceinline__ void mma8(float* c, float a0, float a1, float a2, float a3,
                                     float b0, float b1) {
    asm volatile(
        "mma.sync.aligned.m16n8k8.row.col.f32.tf32.tf32.f32 "
        "{%0,%1,%2,%3}, {%4,%5,%6,%7}, {%8,%9}, {%0,%1,%2,%3};"
        : "+f"(c[0]), "+f"(c[1]), "+f"(c[2]), "+f"(c[3])
        : "r"(__float_as_uint(a0)), "r"(__float_as_uint(a1)),
          "r"(__float_as_uint(a2)), "r"(__float_as_uint(a3)),
          "r"(__float_as_uint(b0)), "r"(__float_as_uint(b1)));
}
// mma.sync m16n8k16 f16 inputs, f32 accum
__device__ __forceinline__ void mma16h(float* c, uint32_t a0, uint32_t a1,
                                       uint32_t a2, uint32_t a3,
                                       uint32_t b0, uint32_t b1) {
    asm volatile(
        "mma.sync.aligned.m16n8k16.row.col.f32.f16.f16.f32 "
        "{%0,%1,%2,%3}, {%4,%5,%6,%7}, {%8,%9}, {%0,%1,%2,%3};"
        : "+f"(c[0]), "+f"(c[1]), "+f"(c[2]), "+f"(c[3])
        : "r"(a0), "r"(a1), "r"(a2), "r"(a3), "r"(b0), "r"(b1));
}

// ============================================================================
// K0: zero the exp-sum accumulators
// ============================================================================
__global__ void k0()
{
    g_sums[threadIdx.x] = 0.f;
}

// ============================================================================
// K1: main GEMM (tf32 mma, x-tile prefetch pipelined) -> relu/gelu;
//     pf = hs@W2^T (tf32 mma); logits = pf@mask^T (tf32 mma) + exp-sum atomics.
// 256 threads, 2 blocks/SM.
// ============================================================================
__global__ __launch_bounds__(256, 2) void k1(
    const float* __restrict__ x, const float* __restrict__ W1, const float* __restrict__ b1,
    const float* __restrict__ W2, const float* __restrict__ b2, const float* __restrict__ mtok,
    const float* __restrict__ Wd, const float* __restrict__ bd)
{
    extern __shared__ float sm[];
    float* Ah = sm, *Bh = sm + 4608;
    float* hs = sm;
    __half* xsh = (__half*)(sm + 8704);
    float* W2s = sm + 12928;
    __shared__ float mt_s[M_ * 68];
    __shared__ float es[M_];

    const int tid   = threadIdx.x;
    const int warp  = tid >> 5, lane = tid & 31;
    const int gID   = lane >> 2, tig = lane & 3;
    const int b     = blockIdx.y;
    const int hw0   = blockIdx.x * 128;
    const int P     = min(128, HW_ - hw0);

    for (int i = tid; i < 512; i += 256) {
        int m = i >> 6, k = i & 63;
        mt_s[m * 68 + k] = tf32r(mtok[m * 64 + k]);
    }
    if (tid < M_) es[tid] = 0.f;

    float c[16][4];
    #pragma unroll
    for (int nt = 0; nt < 16; nt++)
        #pragma unroll
        for (int j = 0; j < 4; j++) c[nt][j] = 0.f;

    const float* xb = x + (size_t)(b * HW_ + hw0) * C_;

    // prefetch chunk 0 x-tile into registers
    float4 pre[4];
    #pragma unroll
    for (int q = 0; q < 4; q++) {
        int i = tid + q * 256;
        int r = i >> 3, qq = i & 7;
        pre[q] = (r < P) ? *(const float4*)(xb + (size_t)r * C_ + qq * 4)
                         : make_float4(0.f, 0.f, 0.f, 0.f);
    }

    for (int ch = 0; ch < 6; ch++) {
        const int k0 = ch * 32;
        __syncthreads();
        // store prefetched A tile (tf32-rounded)
        #pragma unroll
        for (int q = 0; q < 4; q++) {
            int i = tid + q * 256;
            int r = i >> 3, qq = i & 7;
            float4 v = pre[q];
            v.x = tf32r(v.x); v.y = tf32r(v.y); v.z = tf32r(v.z); v.w = tf32r(v.w);
            *(float4*)(Ah + r * 36 + qq * 4) = v;
        }
        // stage B tile
        for (int i = tid; i < 1024; i += 256) {
            int n = i >> 3, q = i & 7;
            const float* src = (n < 64) ? (W1 + n * C_) : (Wd + (n - 64) * C_);
            float4 v = *(const float4*)(src + k0 + q * 4);
            v.x = tf32r(v.x); v.y = tf32r(v.y); v.z = tf32r(v.z); v.w = tf32r(v.w);
            *(float4*)(Bh + n * 36 + q * 4) = v;
        }
        // issue next chunk's x loads (fly during MMA loop)
        if (ch < 5) {
            const int k1n = k0 + 32;
            #pragma unroll
            for (int q = 0; q < 4; q++) {
                int i = tid + q * 256;
                int r = i >> 3, qq = i & 7;
                pre[q] = (r < P) ? *(const float4*)(xb + (size_t)r * C_ + k1n + qq * 4)
                                 : make_float4(0.f, 0.f, 0.f, 0.f);
            }
        }
        __syncthreads();

        const int arow0 = warp * 16 + gID;
        #pragma unroll
        for (int ks = 0; ks < 4; ks++) {
            const int kk = ks * 8;
            float a0 = Ah[arow0 * 36 + kk + tig];
            float a1 = Ah[(arow0 + 8) * 36 + kk + tig];
            float a2 = Ah[arow0 * 36 + kk + tig + 4];
            float a3 = Ah[(arow0 + 8) * 36 + kk + tig + 4];
            #pragma unroll
            for (int nt = 0; nt < 16; nt++) {
                const int bn = nt * 8 + gID;
                float b0 = Bh[bn * 36 + kk + tig];
                float b1 = Bh[bn * 36 + kk + tig + 4];
                mma8(c[nt], a0, a1, a2, a3, b0, b1);
            }
        }
    }
    __syncthreads();   // staging dead; overlay hs/xsh/W2s

    // epilogue: cols 0-63 relu -> hs (tf32-rounded); 64-127 qgelu -> xsh half
    {
        const int p0 = warp * 16 + gID, p1 = p0 + 8;
        #pragma unroll
        for (int nt = 0; nt < 16; nt++) {
            const int n = nt * 8 + tig * 2;
            if (nt < 8) {
                float bia = b1[n], bib = b1[n + 1];
                hs[p0 * 68 + n]     = tf32r(fmaxf(c[nt][0] + bia, 0.f));
                hs[p0 * 68 + n + 1] = tf32r(fmaxf(c[nt][1] + bib, 0.f));
                hs[p1 * 68 + n]     = tf32r(fmaxf(c[nt][2] + bia, 0.f));
                hs[p1 * 68 + n + 1] = tf32r(fmaxf(c[nt][3] + bib, 0.f));
            } else {
                const int d = n - 64;
                float bia = bd[d], bib = bd[d + 1];
                xsh[d * 132 + p0]       = __float2half_rn(qgelu(c[nt][0] + bia));
                xsh[(d + 1) * 132 + p0] = __float2half_rn(qgelu(c[nt][1] + bib));
                xsh[d * 132 + p1]       = __float2half_rn(qgelu(c[nt][2] + bia));
                xsh[(d + 1) * 132 + p1] = __float2half_rn(qgelu(c[nt][3] + bib));
            }
        }
    }
    // stage W2s tf32 [o][k] stride 68
    for (int i = tid; i < 4096; i += 256) {
        int o = i >> 6, kk = i & 63;
        W2s[o * 68 + kk] = tf32r(W2[i]);
    }
    __syncthreads();

    // coalesced g_xp write (half2)
    {
        __half2* xpb = (__half2*)(g_xp + (size_t)b * D_ * HW_ + hw0);
        for (int i = tid; i < 4096; i += 256) {
            int d = i >> 6, pp = i & 63;
            int p = pp * 2;
            if (p < P) {
                __half2 v = __halves2half2(xsh[d * 132 + p], xsh[d * 132 + p + 1]);
                xpb[(size_t)d * (HW_ / 2) + pp] = v;
            }
        }
    }

    // pf = hs @ W2^T via tf32 mma: M=128, N=64, K=64
    float cc[8][4];
    #pragma unroll
    for (int nt = 0; nt < 8; nt++)
        #pragma unroll
        for (int j = 0; j < 4; j++) cc[nt][j] = 0.f;
    {
        const int arow0 = warp * 16 + gID;
        #pragma unroll
        for (int ks = 0; ks < 8; ks++) {
            const int kk = ks * 8;
            float a0 = hs[arow0 * 68 + kk + tig];
            float a1 = hs[(arow0 + 8) * 68 + kk + tig];
            float a2 = hs[arow0 * 68 + kk + tig + 4];
            float a3 = hs[(arow0 + 8) * 68 + kk + tig + 4];
            #pragma unroll
            for (int nt = 0; nt < 8; nt++) {
                const int bn = nt * 8 + gID;
                float b0 = W2s[bn * 68 + kk + tig];
                float b1 = W2s[bn * 68 + kk + tig + 4];
                mma8(cc[nt], a0, a1, a2, a3, b0, b1);
            }
        }
    }
    __syncthreads();   // all pf reads of hs done before overwrite

    // write pf: hs (tf32-rounded, for logits mma) + g_pf (float2)
    {
        const int p0 = warp * 16 + gID, p1 = p0 + 8;
        #pragma unroll
        for (int nt = 0; nt < 8; nt++) {
            const int n = nt * 8 + tig * 2;
            float bia = b2[n], bib = b2[n + 1];
            float v00 = cc[nt][0] + bia, v01 = cc[nt][1] + bib;
            float v10 = cc[nt][2] + bia, v11 = cc[nt][3] + bib;
            hs[p0 * 68 + n]     = tf32r(v00);
            hs[p0 * 68 + n + 1] = tf32r(v01);
            hs[p1 * 68 + n]     = tf32r(v10);
            hs[p1 * 68 + n + 1] = tf32r(v11);
            if (p0 < P)
                *(float2*)(g_pf + (size_t)(b * HW_ + hw0 + p0) * 64 + n) = make_float2(v00, v01);
            if (p1 < P)
                *(float2*)(g_pf + (size_t)(b * HW_ + hw0 + p1) * 64 + n) = make_float2(v10, v11);
        }
    }
    __syncthreads();

    // logits = pf @ mask^T via tf32 mma + per-block exp-sum accumulation
    {
        float cl[4] = {0.f, 0.f, 0.f, 0.f};
        const int arow0 = warp * 16 + gID;
        #pragma unroll
        for (int ks = 0; ks < 8; ks++) {
            const int kk = ks * 8;
            float a0 = hs[arow0 * 68 + kk + tig];
            float a1 = hs[(arow0 + 8) * 68 + kk + tig];
            float a2 = hs[arow0 * 68 + kk + tig + 4];
            float a3 = hs[(arow0 + 8) * 68 + kk + tig + 4];
            float b0 = mt_s[gID * 68 + kk + tig];
            float b1 = mt_s[gID * 68 + kk + tig + 4];
            mma8(cl, a0, a1, a2, a3, b0, b1);
        }
        const int p0 = warp * 16 + gID, p1 = p0 + 8;
        const int m0 = tig * 2, m1 = tig * 2 + 1;
        float e0 = 0.f, e1 = 0.f;
        if (p0 < P) {
            g_logits[(size_t)(m0 * B_ + b) * HW_ + hw0 + p0] = cl[0];
            g_logits[(size_t)(m1 * B_ + b) * HW_ + hw0 + p0] = cl[1];
            e0 += __expf(cl[0]); e1 += __expf(cl[1]);
        }
        if (p1 < P) {
            g_logits[(size_t)(m0 * B_ + b) * HW_ + hw0 + p1] = cl[2];
            g_logits[(size_t)(m1 * B_ + b) * HW_ + hw0 + p1] = cl[3];
            e0 += __expf(cl[2]); e1 += __expf(cl[3]);
        }
        // reduce within quad-column first via shuffles (lanes with same tig spread)
        atomicAdd(&es[m0], e0);
        atomicAdd(&es[m1], e1);
        __syncthreads();
        if (tid < M_) atomicAdd(&g_sums[tid * B_ + b], es[tid]);
    }
}

// ============================================================================
// K3a: partial mwf over 392-position chunks. grid (8, 32)
// ============================================================================
__global__ __launch_bounds__(256) void k3a()
{
    const int chunk = blockIdx.x, b = blockIdx.y;
    const int tid = threadIdx.x;
    const int p0 = chunk * 392;
    __shared__ float ms[392];
    __shared__ float izs[M_];
    __shared__ float red[4][64];

    if (tid < M_) izs[tid] = 1.f / g_sums[tid * B_ + b];
    __syncthreads();

    for (int p = tid; p < 392; p += 256) {
        float s = 0.f;
        #pragma unroll
        for (int m = 0; m < M_; m++)
            s += __expf(g_logits[(size_t)(m * B_ + b) * HW_ + p0 + p]) * izs[m];
        ms[p] = s;
    }
    __syncthreads();

    int k = tid & 63, g = tid >> 6;
    float acc = 0.f;
    const float* pfb = g_pf + (size_t)(b * HW_ + p0) * 64;
    for (int p = g; p < 392; p += 4)
        acc = fmaf(ms[p], pfb[(size_t)p * 64 + k], acc);
    red[g][k] = acc;
    __syncthreads();
    if (g == 0)
        g_part[(b * 8 + chunk) * 64 + k] = red[0][k] + red[1][k] + red[2][k] + red[3][k];
}

// ============================================================================
// K4: reduce g_part -> mwf (smem), then conv_w[b,o] = mwf[b].Wh[o] + bh[o]
// ============================================================================
__global__ __launch_bounds__(256) void k4(const float* __restrict__ Wh,
                                          const float* __restrict__ bh)
{
    __shared__ float ms[2048];
    int tid = threadIdx.x;
    for (int i = tid; i < 2048; i += 256) {
        int bb = i >> 6, k = i & 63;
        float acc = 0.f;
        #pragma unroll
        for (int cch = 0; cch < 8; cch++) acc += g_part[(bb * 8 + cch) * 64 + k];
        ms[i] = acc;
    }
    __syncthreads();

    int o = blockIdx.x * 256 + tid;
    float4 wv[16];
    const float4* wr = (const float4*)(Wh + (size_t)o * 64);
    #pragma unroll
    for (int q = 0; q < 16; q++) wv[q] = wr[q];
    const float* wf = (const float*)wv;
    float bias = bh[o];

    for (int b = 0; b < B_; b++) {
        float acc = bias;
        const float* mb = ms + b * 64;
        #pragma unroll
        for (int kk = 0; kk < 64; kk++) acc = fmaf(mb[kk], wf[kk], acc);
        g_convw[(size_t)b * 36864 + o] = acc;
    }
}

// ============================================================================
// K5: conv (f16 m16n8k16 mma) + quickGELU + up-proj (f16 mma) + residual.
// tile 8 rows x 32 cols = 256 positions (m = c*8+r), 256 threads, 2 blocks/SM.
// ============================================================================
__global__ __launch_bounds__(256, 2) void k5(const float* __restrict__ x,
                                             const float* __restrict__ Wu,
                                             const float* __restrict__ bu,
                                             float* __restrict__ out)
{
    extern __shared__ float sm[];
    __half* hbase = (__half*)sm;
    __half* hin_h = hbase;             // [340 spatial][20] halves (13600 B)
    __half* Bw_h  = hbase + 6800;      // [576][24] halves (27648 B)
    __half* gbuf  = hbase;             // overlay: [256 m][72] halves (36864 B)
    __half* wuh   = hbase + 18432;     // overlay: [192 n][72] halves (27648 B)
    __shared__ float bus[C_];

    const int tid  = threadIdx.x;
    const int warp = tid >> 5, lane = tid & 31;
    const int gID  = lane >> 2, tig = lane & 3;
    const int b    = blockIdx.y;
    const int t    = blockIdx.x;          // 0..13
    const int row0 = (t % 7) * 8;
    const int col0 = (t / 7) * 24;        // {0, 24}; cols overlap (benign dup)

    for (int i = tid; i < C_; i += 256) bus[i] = bu[i];

    float c[2][8][4];
    #pragma unroll
    for (int mtl = 0; mtl < 2; mtl++)
        #pragma unroll
        for (int nt = 0; nt < 8; nt++)
            #pragma unroll
            for (int j = 0; j < 4; j++) c[mtl][nt][j] = 0.f;

    for (int ci = 0; ci < 4; ci++) {
        __syncthreads();
        // stage halo input [10][34] x 16 ic (half2 per ic-pair)
        for (int i = tid; i < 2720; i += 256) {
            int s = i >> 3, jc = i & 7;
            int hr = s / 34, hc = s % 34;
            int gy = row0 - 1 + hr, gx = col0 - 1 + hc;
            __half2 v = __halves2half2(__float2half(0.f), __float2half(0.f));
            if (gy >= 0 && gy < H_ && gx >= 0 && gx < W_) {
                size_t base = (size_t)(b * D_ + ci * 16 + 2 * jc) * HW_ + gy * W_ + gx;
                v = __halves2half2(g_xp[base], g_xp[base + HW_]);
            }
            *(__half2*)(hin_h + s * 20 + 2 * jc) = v;
        }
        // stage weights Bw_h[(tap*64+oc)][ic] halves
        for (int i = tid; i < 9216; i += 256) {
            int ic = i & 15, rest = i >> 4;
            int oc = rest & 63, tap = rest >> 6;
            Bw_h[rest * 24 + ic] =
                __float2half_rn(g_convw[(size_t)b * 36864 + oc * 576 + (ci * 16 + ic) * 9 + tap]);
        }
        __syncthreads();

        #pragma unroll
        for (int tap = 0; tap < 9; tap++) {
            const int dy = tap / 3, dx = tap % 3;
            uint32_t a[2][4];
            #pragma unroll
            for (int mtl = 0; mtl < 2; mtl++) {
                const __half* ap = hin_h +
                    ((gID + dy) * 34 + 4 * warp + 2 * mtl + dx) * 20 + 2 * tig;
                a[mtl][0] = *(const uint32_t*)(ap);
                a[mtl][1] = *(const uint32_t*)(ap + 20);   // m+8 (next spatial col)
                a[mtl][2] = *(const uint32_t*)(ap + 8);    // k+8
                a[mtl][3] = *(const uint32_t*)(ap + 28);
            }
            #pragma unroll
            for (int nt = 0; nt < 8; nt++) {
                const __half* bp = Bw_h + (tap * 64 + nt * 8 + gID) * 24 + 2 * tig;
                uint32_t b0 = *(const uint32_t*)(bp);
                uint32_t b1 = *(const uint32_t*)(bp + 8);
                mma16h(c[0][nt], a[0][0], a[0][1], a[0][2], a[0][3], b0, b1);
                mma16h(c[1][nt], a[1][0], a[1][1], a[1][2], a[1][3], b0, b1);
            }
        }
    }
    __syncthreads();   // conv done; overlay gbuf/wuh

    // quickGELU -> gbuf half2, stride 72
    #pragma unroll
    for (int mtl = 0; mtl < 2; mtl++) {
        int m0 = (2 * warp + mtl) * 16 + gID;
        #pragma unroll
        for (int nt = 0; nt < 8; nt++) {
            int oc = nt * 8 + tig * 2;
            *(__half2*)(gbuf + m0 * 72 + oc) =
                __floats2half2_rn(qgelu(c[mtl][nt][0]), qgelu(c[mtl][nt][1]));
            *(__half2*)(gbuf + (m0 + 8) * 72 + oc) =
                __floats2half2_rn(qgelu(c[mtl][nt][2]), qgelu(c[mtl][nt][3]));
        }
    }
    // stage Wu as half: wuh[n][k]
    for (int i = tid; i < 12288; i += 256) {
        int n = i >> 6, k = i & 63;
        wuh[n * 72 + k] = __float2half_rn(Wu[i]);
    }
    __syncthreads();

    // up-proj: D[256 pos][192 ch] = gbuf @ wuh^T via f16 mma, 3 passes of 64 ch
    for (int pass = 0; pass < 3; pass++) {
        float cc[2][8][4];
        #pragma unroll
        for (int mtl = 0; mtl < 2; mtl++)
            #pragma unroll
            for (int nt = 0; nt < 8; nt++)
                #pragma unroll
                for (int j = 0; j < 4; j++) cc[mtl][nt][j] = 0.f;

        #pragma unroll
        for (int ks = 0; ks < 4; ks++) {
            const int k0 = ks * 16;
            uint32_t a[2][4];
            #pragma unroll
            for (int mtl = 0; mtl < 2; mtl++) {
                int r0 = (warp * 2 + mtl) * 16 + gID;
                const __half* g0 = gbuf + r0 * 72 + k0 + tig * 2;
                a[mtl][0] = *(const uint32_t*)(g0);
                a[mtl][1] = *(const uint32_t*)(g0 + 8 * 72);
                a[mtl][2] = *(const uint32_t*)(g0 + 8);
                a[mtl][3] = *(const uint32_t*)(g0 + 8 * 72 + 8);
            }
            #pragma unroll
            for (int nt = 0; nt < 8; nt++) {
                const __half* w0 = wuh + (pass * 64 + nt * 8 + gID) * 72 + k0 + tig * 2;
                uint32_t b0 = *(const uint32_t*)(w0);
                uint32_t b1 = *(const uint32_t*)(w0 + 8);
                mma16h(cc[0][nt], a[0][0], a[0][1], a[0][2], a[0][3], b0, b1);
                mma16h(cc[1][nt], a[1][0], a[1][1], a[1][2], a[1][3], b0, b1);
            }
        }
        // epilogue: residual + bias, direct float2 stores
        #pragma unroll
        for (int mtl = 0; mtl < 2; mtl++) {
            #pragma unroll
            for (int hf = 0; hf < 2; hf++) {
                int m = (warp * 2 + mtl) * 16 + gID + hf * 8;
                int gy = row0 + (m & 7), gx = col0 + (m >> 3);
                size_t n = (size_t)b * HW_ + gy * W_ + gx;
                const float* xr = x + n * C_;
                float* orr = out + n * C_;
                #pragma unroll
                for (int nt = 0; nt < 8; nt++) {
                    int chn = pass * 64 + nt * 8 + tig * 2;
                    float2 xv = *(const float2*)(xr + chn);
                    float v0 = cc[mtl][nt][hf * 2 + 0] + bus[chn]     + xv.x;
                    float v1 = cc[mtl][nt][hf * 2 + 1] + bus[chn + 1] + xv.y;
                    *(float2*)(orr + chn) = make_float2(v0, v1);
                }
            }
        }
    }
}

// ============================================================================
extern "C" void kernel_launch(void* const* d_in, const int* in_sizes, int n_in,
                              void* d_out, int out_size)
{
    const float* x  = (const float*)d_in[0];
    const float* W1 = (const float*)d_in[1];
    const float* b1 = (const float*)d_in[2];
    const float* W2 = (const float*)d_in[3];
    const float* b2 = (const float*)d_in[4];
    const float* mt = (const float*)d_in[5];
    const float* Wh = (const float*)d_in[6];
    const float* bh = (const float*)d_in[7];
    const float* Wd = (const float*)d_in[8];
    const float* bd = (const float*)d_in[9];
    const float* Wu = (const float*)d_in[10];
    const float* bu = (const float*)d_in[11];
    float* out = (float*)d_out;

    cudaFuncSetAttribute(k1, cudaFuncAttributeMaxDynamicSharedMemorySize, 69120);
    cudaFuncSetAttribute(k5, cudaFuncAttributeMaxDynamicSharedMemorySize, 64512);

    k0<<<1, 256>>>();
    k1<<<dim3(25, 32), 256, 69120>>>(x, W1, b1, W2, b2, mt, Wd, bd);
    k3a<<<dim3(8, 32), 256>>>();
    k4<<<144, 256>>>(Wh, bh);
    k5<<<dim3(14, 32), 256, 64512>>>(x, Wu, bu, out);
}

// round 15
// speedup vs baseline: 1.5977x; 1.0441x over previous
#include <cuda_runtime.h>
#include <cuda_fp16.h>
#include <math.h>
#include <stdint.h>

#define B_  32
#define H_  56
#define W_  56
#define C_  192
#define D_  64
#define M_  8
#define HW_ 3136
#define N_  (B_*HW_)

// ---------------- device scratch (no allocations allowed) ----------------
__device__ float  g_pf[(size_t)N_ * 64];            // [n][64]
__device__ __half g_xp[(size_t)B_ * D_ * HW_];      // [b][d][hw] half
__device__ float  g_logits[(size_t)M_ * B_ * HW_];  // [m][b][hw]
__device__ float  g_sums[M_ * B_];                  // per (m,b): sum of exp
__device__ float  g_part[B_ * 8 * 64];              // partial mwf
__device__ __half g_convwh[(size_t)B_ * 36864];     // [b][oc*576+ic*9+tap] half

__device__ __forceinline__ float qgelu(float v) {
    return v / (1.f + __expf(-1.702f * v));
}
// mma.sync m16n8k16 f16 inputs, f32 accum
__device__ __forceinline__ void mma16h(float* c, uint32_t a0, uint32_t a1,
                                       uint32_t a2, uint32_t a3,
                                       uint32_t b0, uint32_t b1) {
    asm volatile(
        "mma.sync.aligned.m16n8k16.row.col.f32.f16.f16.f32 "
        "{%0,%1,%2,%3}, {%4,%5,%6,%7}, {%8,%9}, {%0,%1,%2,%3};"
        : "+f"(c[0]), "+f"(c[1]), "+f"(c[2]), "+f"(c[3])
        : "r"(a0), "r"(a1), "r"(a2), "r"(a3), "r"(b0), "r"(b1));
}

// ============================================================================
// K0: zero the exp-sum accumulators
// ============================================================================
__global__ void k0()
{
    g_sums[threadIdx.x] = 0.f;
}

// ============================================================================
// K1: main GEMM (f16 mma, x prefetch) -> relu/gelu; pf = hs@W2^T (f16 mma);
//     logits = pf@mask^T (f16 mma) + exp-sum atomics. 256 threads, 2 blk/SM.
// ============================================================================
__global__ __launch_bounds__(256, 2) void k1(
    const float* __restrict__ x, const float* __restrict__ W1, const float* __restrict__ b1,
    const float* __restrict__ W2, const float* __restrict__ b2, const float* __restrict__ mtok,
    const float* __restrict__ Wd, const float* __restrict__ bd)
{
    extern __shared__ __align__(16) char smraw[];
    __half* Ah  = (__half*)smraw;            // [128][40]
    __half* Bh  = (__half*)smraw + 5120;     // [128][40]
    __half* hs  = (__half*)smraw;            // overlay: [128][72]
    __half* xsh = (__half*)smraw + 9216;     // [64][132]
    __half* W2s = (__half*)smraw + 17664;    // [64][72]
    __shared__ __half mt_s[M_ * 72];
    __shared__ float es[M_];

    const int tid   = threadIdx.x;
    const int warp  = tid >> 5, lane = tid & 31;
    const int gID   = lane >> 2, tig = lane & 3;
    const int b     = blockIdx.y;
    const int hw0   = blockIdx.x * 128;
    const int P     = min(128, HW_ - hw0);

    for (int i = tid; i < 512; i += 256) {
        int m = i >> 6, k = i & 63;
        mt_s[m * 72 + k] = __float2half_rn(mtok[m * 64 + k]);
    }
    if (tid < M_) es[tid] = 0.f;

    float c[16][4];
    #pragma unroll
    for (int nt = 0; nt < 16; nt++)
        #pragma unroll
        for (int j = 0; j < 4; j++) c[nt][j] = 0.f;

    const float* xb = x + (size_t)(b * HW_ + hw0) * C_;

    // prefetch chunk 0 x-tile into registers
    float4 pre[4];
    #pragma unroll
    for (int q = 0; q < 4; q++) {
        int i = tid + q * 256;
        int r = i >> 3, qq = i & 7;
        pre[q] = (r < P) ? *(const float4*)(xb + (size_t)r * C_ + qq * 4)
                         : make_float4(0.f, 0.f, 0.f, 0.f);
    }

    for (int ch = 0; ch < 6; ch++) {
        const int k0 = ch * 32;
        __syncthreads();
        // store prefetched A tile (half)
        #pragma unroll
        for (int q = 0; q < 4; q++) {
            int i = tid + q * 256;
            int r = i >> 3, qq = i & 7;
            float4 v = pre[q];
            __half2* dst = (__half2*)(Ah + r * 40 + qq * 4);
            dst[0] = __floats2half2_rn(v.x, v.y);
            dst[1] = __floats2half2_rn(v.z, v.w);
        }
        // stage B tile (half)
        for (int i = tid; i < 1024; i += 256) {
            int n = i >> 3, q = i & 7;
            const float* src = (n < 64) ? (W1 + n * C_) : (Wd + (n - 64) * C_);
            float4 v = *(const float4*)(src + k0 + q * 4);
            __half2* dst = (__half2*)(Bh + n * 40 + q * 4);
            dst[0] = __floats2half2_rn(v.x, v.y);
            dst[1] = __floats2half2_rn(v.z, v.w);
        }
        // issue next chunk's x loads
        if (ch < 5) {
            const int k1n = k0 + 32;
            #pragma unroll
            for (int q = 0; q < 4; q++) {
                int i = tid + q * 256;
                int r = i >> 3, qq = i & 7;
                pre[q] = (r < P) ? *(const float4*)(xb + (size_t)r * C_ + k1n + qq * 4)
                                 : make_float4(0.f, 0.f, 0.f, 0.f);
            }
        }
        __syncthreads();

        const int arow = warp * 16 + gID;
        #pragma unroll
        for (int ks = 0; ks < 2; ks++) {
            const int kk = ks * 16;
            const __half* ap = Ah + arow * 40 + kk + 2 * tig;
            uint32_t a0 = *(const uint32_t*)(ap);
            uint32_t a1 = *(const uint32_t*)(ap + 8 * 40);
            uint32_t a2 = *(const uint32_t*)(ap + 8);
            uint32_t a3 = *(const uint32_t*)(ap + 8 * 40 + 8);
            #pragma unroll
            for (int nt = 0; nt < 16; nt++) {
                const __half* bp = Bh + (nt * 8 + gID) * 40 + kk + 2 * tig;
                uint32_t b0 = *(const uint32_t*)(bp);
                uint32_t b1 = *(const uint32_t*)(bp + 8);
                mma16h(c[nt], a0, a1, a2, a3, b0, b1);
            }
        }
    }
    __syncthreads();   // staging dead; overlay hs/xsh/W2s

    // epilogue: cols 0-63 relu -> hs (half); 64-127 qgelu -> xsh half
    {
        const int p0 = warp * 16 + gID, p1 = p0 + 8;
        #pragma unroll
        for (int nt = 0; nt < 16; nt++) {
            const int n = nt * 8 + tig * 2;
            if (nt < 8) {
                float bia = b1[n], bib = b1[n + 1];
                *(__half2*)(hs + p0 * 72 + n) =
                    __floats2half2_rn(fmaxf(c[nt][0] + bia, 0.f), fmaxf(c[nt][1] + bib, 0.f));
                *(__half2*)(hs + p1 * 72 + n) =
                    __floats2half2_rn(fmaxf(c[nt][2] + bia, 0.f), fmaxf(c[nt][3] + bib, 0.f));
            } else {
                const int d = n - 64;
                float bia = bd[d], bib = bd[d + 1];
                xsh[d * 132 + p0]       = __float2half_rn(qgelu(c[nt][0] + bia));
                xsh[(d + 1) * 132 + p0] = __float2half_rn(qgelu(c[nt][1] + bib));
                xsh[d * 132 + p1]       = __float2half_rn(qgelu(c[nt][2] + bia));
                xsh[(d + 1) * 132 + p1] = __float2half_rn(qgelu(c[nt][3] + bib));
            }
        }
    }
    // stage W2s half [o][k] stride 72
    for (int i = tid; i < 4096; i += 256) {
        int o = i >> 6, kk = i & 63;
        W2s[o * 72 + kk] = __float2half_rn(W2[i]);
    }
    __syncthreads();

    // coalesced g_xp write (half2)
    {
        __half2* xpb = (__half2*)(g_xp + (size_t)b * D_ * HW_ + hw0);
        for (int i = tid; i < 4096; i += 256) {
            int d = i >> 6, pp = i & 63;
            int p = pp * 2;
            if (p < P) {
                __half2 v = __halves2half2(xsh[d * 132 + p], xsh[d * 132 + p + 1]);
                xpb[(size_t)d * (HW_ / 2) + pp] = v;
            }
        }
    }

    // pf = hs @ W2^T via f16 mma: M=128, N=64, K=64
    float cc[8][4];
    #pragma unroll
    for (int nt = 0; nt < 8; nt++)
        #pragma unroll
        for (int j = 0; j < 4; j++) cc[nt][j] = 0.f;
    {
        const int arow = warp * 16 + gID;
        #pragma unroll
        for (int ks = 0; ks < 4; ks++) {
            const int kk = ks * 16;
            const __half* ap = hs + arow * 72 + kk + 2 * tig;
            uint32_t a0 = *(const uint32_t*)(ap);
            uint32_t a1 = *(const uint32_t*)(ap + 8 * 72);
            uint32_t a2 = *(const uint32_t*)(ap + 8);
            uint32_t a3 = *(const uint32_t*)(ap + 8 * 72 + 8);
            #pragma unroll
            for (int nt = 0; nt < 8; nt++) {
                const __half* bp = W2s + (nt * 8 + gID) * 72 + kk + 2 * tig;
                uint32_t b0 = *(const uint32_t*)(bp);
                uint32_t b1 = *(const uint32_t*)(bp + 8);
                mma16h(cc[nt], a0, a1, a2, a3, b0, b1);
            }
        }
    }
    __syncthreads();   // all pf reads of hs done before overwrite

    // write pf: hs (half, for logits mma) + g_pf (float2)
    {
        const int p0 = warp * 16 + gID, p1 = p0 + 8;
        #pragma unroll
        for (int nt = 0; nt < 8; nt++) {
            const int n = nt * 8 + tig * 2;
            float bia = b2[n], bib = b2[n + 1];
            float v00 = cc[nt][0] + bia, v01 = cc[nt][1] + bib;
            float v10 = cc[nt][2] + bia, v11 = cc[nt][3] + bib;
            *(__half2*)(hs + p0 * 72 + n) = __floats2half2_rn(v00, v01);
            *(__half2*)(hs + p1 * 72 + n) = __floats2half2_rn(v10, v11);
            if (p0 < P)
                *(float2*)(g_pf + (size_t)(b * HW_ + hw0 + p0) * 64 + n) = make_float2(v00, v01);
            if (p1 < P)
                *(float2*)(g_pf + (size_t)(b * HW_ + hw0 + p1) * 64 + n) = make_float2(v10, v11);
        }
    }
    __syncthreads();

    // logits = pf @ mask^T via f16 mma + exp-sum accumulation
    {
        float cl[4] = {0.f, 0.f, 0.f, 0.f};
        const int arow = warp * 16 + gID;
        #pragma unroll
        for (int ks = 0; ks < 4; ks++) {
            const int kk = ks * 16;
            const __half* ap = hs + arow * 72 + kk + 2 * tig;
            uint32_t a0 = *(const uint32_t*)(ap);
            uint32_t a1 = *(const uint32_t*)(ap + 8 * 72);
            uint32_t a2 = *(const uint32_t*)(ap + 8);
            uint32_t a3 = *(const uint32_t*)(ap + 8 * 72 + 8);
            const __half* bp = mt_s + gID * 72 + kk + 2 * tig;
            uint32_t b0 = *(const uint32_t*)(bp);
            uint32_t b1 = *(const uint32_t*)(bp + 8);
            mma16h(cl, a0, a1, a2, a3, b0, b1);
        }
        const int p0 = warp * 16 + gID, p1 = p0 + 8;
        const int m0 = tig * 2, m1 = tig * 2 + 1;
        float e0 = 0.f, e1 = 0.f;
        if (p0 < P) {
            g_logits[(size_t)(m0 * B_ + b) * HW_ + hw0 + p0] = cl[0];
            g_logits[(size_t)(m1 * B_ + b) * HW_ + hw0 + p0] = cl[1];
            e0 += __expf(cl[0]); e1 += __expf(cl[1]);
        }
        if (p1 < P) {
            g_logits[(size_t)(m0 * B_ + b) * HW_ + hw0 + p1] = cl[2];
            g_logits[(size_t)(m1 * B_ + b) * HW_ + hw0 + p1] = cl[3];
            e0 += __expf(cl[2]); e1 += __expf(cl[3]);
        }
        atomicAdd(&es[m0], e0);
        atomicAdd(&es[m1], e1);
        __syncthreads();
        if (tid < M_) atomicAdd(&g_sums[tid * B_ + b], es[tid]);
    }
}

// ============================================================================
// K3a: partial mwf over 392-position chunks. grid (8, 32)
// ============================================================================
__global__ __launch_bounds__(256) void k3a()
{
    const int chunk = blockIdx.x, b = blockIdx.y;
    const int tid = threadIdx.x;
    const int p0 = chunk * 392;
    __shared__ float ms[392];
    __shared__ float izs[M_];
    __shared__ float red[4][64];

    if (tid < M_) izs[tid] = 1.f / g_sums[tid * B_ + b];
    __syncthreads();

    for (int p = tid; p < 392; p += 256) {
        float s = 0.f;
        #pragma unroll
        for (int m = 0; m < M_; m++)
            s += __expf(g_logits[(size_t)(m * B_ + b) * HW_ + p0 + p]) * izs[m];
        ms[p] = s;
    }
    __syncthreads();

    int k = tid & 63, g = tid >> 6;
    float acc = 0.f;
    const float* pfb = g_pf + (size_t)(b * HW_ + p0) * 64;
    for (int p = g; p < 392; p += 4)
        acc = fmaf(ms[p], pfb[(size_t)p * 64 + k], acc);
    red[g][k] = acc;
    __syncthreads();
    if (g == 0)
        g_part[(b * 8 + chunk) * 64 + k] = red[0][k] + red[1][k] + red[2][k] + red[3][k];
}

// ============================================================================
// K4: reduce g_part -> mwf (half smem); conv_w = Wh @ mwf^T via f16 mma;
// smem-transposed coalesced half output. 144 blocks x 256 threads.
// ============================================================================
__global__ __launch_bounds__(256) void k4(const float* __restrict__ Wh,
                                          const float* __restrict__ bh)
{
    extern __shared__ __align__(16) char smraw[];
    __half* mwh = (__half*)smraw;            // [32][72]  (4608 B)
    __half* whs = (__half*)smraw + 2304;     // [256][72] (36864 B)
    __half* cs  = (__half*)smraw + 2304;     // overlay after mma: [256][34]

    const int tid  = threadIdx.x;
    const int warp = tid >> 5, lane = tid & 31;
    const int gID  = lane >> 2, tig = lane & 3;
    const int o0   = blockIdx.x * 256;

    // reduce partial mwf -> mwh (half)
    for (int i = tid; i < 2048; i += 256) {
        int bb = i >> 6, k = i & 63;
        float acc = 0.f;
        #pragma unroll
        for (int cch = 0; cch < 8; cch++) acc += g_part[(bb * 8 + cch) * 64 + k];
        mwh[bb * 72 + k] = __float2half_rn(acc);
    }
    // stage Wh tile (coalesced float reads -> half)
    for (int i = tid; i < 16384; i += 256) {
        int row = i >> 6, k = i & 63;
        whs[row * 72 + k] = __float2half_rn(Wh[(size_t)(o0 + row) * 64 + k]);
    }
    __syncthreads();

    // mma: M=256 (warp owns 2 m-tiles), N=32, K=64
    float cc[2][4][4];
    #pragma unroll
    for (int mtl = 0; mtl < 2; mtl++)
        #pragma unroll
        for (int nt = 0; nt < 4; nt++)
            #pragma unroll
            for (int j = 0; j < 4; j++) cc[mtl][nt][j] = 0.f;

    #pragma unroll
    for (int ks = 0; ks < 4; ks++) {
        const int kk = ks * 16;
        uint32_t a[2][4];
        #pragma unroll
        for (int mtl = 0; mtl < 2; mtl++) {
            const __half* ap = whs + (warp * 32 + mtl * 16 + gID) * 72 + kk + 2 * tig;
            a[mtl][0] = *(const uint32_t*)(ap);
            a[mtl][1] = *(const uint32_t*)(ap + 8 * 72);
            a[mtl][2] = *(const uint32_t*)(ap + 8);
            a[mtl][3] = *(const uint32_t*)(ap + 8 * 72 + 8);
        }
        #pragma unroll
        for (int nt = 0; nt < 4; nt++) {
            const __half* bp = mwh + (nt * 8 + gID) * 72 + kk + 2 * tig;
            uint32_t b0 = *(const uint32_t*)(bp);
            uint32_t b1 = *(const uint32_t*)(bp + 8);
            mma16h(cc[0][nt], a[0][0], a[0][1], a[0][2], a[0][3], b0, b1);
            mma16h(cc[1][nt], a[1][0], a[1][1], a[1][2], a[1][3], b0, b1);
        }
    }
    __syncthreads();   // whs reads done; overlay cs

    // bias + transpose to cs[o_local][b]
    #pragma unroll
    for (int mtl = 0; mtl < 2; mtl++) {
        int r0 = warp * 32 + mtl * 16 + gID;
        float bia0 = bh[o0 + r0], bia1 = bh[o0 + r0 + 8];
        #pragma unroll
        for (int nt = 0; nt < 4; nt++) {
            int col = nt * 8 + tig * 2;
            cs[r0 * 34 + col]           = __float2half_rn(cc[mtl][nt][0] + bia0);
            cs[r0 * 34 + col + 1]       = __float2half_rn(cc[mtl][nt][1] + bia0);
            cs[(r0 + 8) * 34 + col]     = __float2half_rn(cc[mtl][nt][2] + bia1);
            cs[(r0 + 8) * 34 + col + 1] = __float2half_rn(cc[mtl][nt][3] + bia1);
        }
    }
    __syncthreads();

    // coalesced half writes
    for (int i = tid; i < 8192; i += 256) {
        int b = i >> 8, ol = i & 255;
        g_convwh[(size_t)b * 36864 + o0 + ol] = cs[ol * 34 + b];
    }
}

// ============================================================================
// K5: conv (f16 m16n8k16 mma) + quickGELU + up-proj (f16 mma) + residual.
// tile 8 rows x 32 cols = 256 positions (m = c*8+r), 256 threads, 2 blocks/SM.
// ============================================================================
__global__ __launch_bounds__(256, 2) void k5(const float* __restrict__ x,
                                             const float* __restrict__ Wu,
                                             const float* __restrict__ bu,
                                             float* __restrict__ out)
{
    extern __shared__ float sm[];
    __half* hbase = (__half*)sm;
    __half* hin_h = hbase;             // [340 spatial][20] halves (13600 B)
    __half* Bw_h  = hbase + 6800;      // [576][24] halves (27648 B)
    __half* gbuf  = hbase;             // overlay: [256 m][72] halves (36864 B)
    __half* wuh   = hbase + 18432;     // overlay: [192 n][72] halves (27648 B)
    __shared__ float bus[C_];

    const int tid  = threadIdx.x;
    const int warp = tid >> 5, lane = tid & 31;
    const int gID  = lane >> 2, tig = lane & 3;
    const int b    = blockIdx.y;
    const int t    = blockIdx.x;          // 0..13
    const int row0 = (t % 7) * 8;
    const int col0 = (t / 7) * 24;        // {0, 24}; cols overlap (benign dup)

    for (int i = tid; i < C_; i += 256) bus[i] = bu[i];

    float c[2][8][4];
    #pragma unroll
    for (int mtl = 0; mtl < 2; mtl++)
        #pragma unroll
        for (int nt = 0; nt < 8; nt++)
            #pragma unroll
            for (int j = 0; j < 4; j++) c[mtl][nt][j] = 0.f;

    for (int ci = 0; ci < 4; ci++) {
        __syncthreads();
        // stage halo input [10][34] x 16 ic (half2 per ic-pair)
        for (int i = tid; i < 2720; i += 256) {
            int s = i >> 3, jc = i & 7;
            int hr = s / 34, hc = s % 34;
            int gy = row0 - 1 + hr, gx = col0 - 1 + hc;
            __half2 v = __halves2half2(__float2half(0.f), __float2half(0.f));
            if (gy >= 0 && gy < H_ && gx >= 0 && gx < W_) {
                size_t base = (size_t)(b * D_ + ci * 16 + 2 * jc) * HW_ + gy * W_ + gx;
                v = __halves2half2(g_xp[base], g_xp[base + HW_]);
            }
            *(__half2*)(hin_h + s * 20 + 2 * jc) = v;
        }
        // stage weights Bw_h[(tap*64+oc)][ic] (direct half copy)
        for (int i = tid; i < 9216; i += 256) {
            int ic = i & 15, rest = i >> 4;
            int oc = rest & 63, tap = rest >> 6;
            Bw_h[rest * 24 + ic] =
                g_convwh[(size_t)b * 36864 + oc * 576 + (ci * 16 + ic) * 9 + tap];
        }
        __syncthreads();

        #pragma unroll
        for (int tap = 0; tap < 9; tap++) {
            const int dy = tap / 3, dx = tap % 3;
            uint32_t a[2][4];
            #pragma unroll
            for (int mtl = 0; mtl < 2; mtl++) {
                const __half* ap = hin_h +
                    ((gID + dy) * 34 + 4 * warp + 2 * mtl + dx) * 20 + 2 * tig;
                a[mtl][0] = *(const uint32_t*)(ap);
                a[mtl][1] = *(const uint32_t*)(ap + 20);
                a[mtl][2] = *(const uint32_t*)(ap + 8);
                a[mtl][3] = *(const uint32_t*)(ap + 28);
            }
            #pragma unroll
            for (int nt = 0; nt < 8; nt++) {
                const __half* bp = Bw_h + (tap * 64 + nt * 8 + gID) * 24 + 2 * tig;
                uint32_t b0 = *(const uint32_t*)(bp);
                uint32_t b1 = *(const uint32_t*)(bp + 8);
                mma16h(c[0][nt], a[0][0], a[0][1], a[0][2], a[0][3], b0, b1);
                mma16h(c[1][nt], a[1][0], a[1][1], a[1][2], a[1][3], b0, b1);
            }
        }
    }
    __syncthreads();   // conv done; overlay gbuf/wuh

    // quickGELU -> gbuf half2, stride 72
    #pragma unroll
    for (int mtl = 0; mtl < 2; mtl++) {
        int m0 = (2 * warp + mtl) * 16 + gID;
        #pragma unroll
        for (int nt = 0; nt < 8; nt++) {
            int oc = nt * 8 + tig * 2;
            *(__half2*)(gbuf + m0 * 72 + oc) =
                __floats2half2_rn(qgelu(c[mtl][nt][0]), qgelu(c[mtl][nt][1]));
            *(__half2*)(gbuf + (m0 + 8) * 72 + oc) =
                __floats2half2_rn(qgelu(c[mtl][nt][2]), qgelu(c[mtl][nt][3]));
        }
    }
    // stage Wu as half: wuh[n][k]
    for (int i = tid; i < 12288; i += 256) {
        int n = i >> 6, k = i & 63;
        wuh[n * 72 + k] = __float2half_rn(Wu[i]);
    }
    __syncthreads();

    // up-proj: D[256 pos][192 ch] = gbuf @ wuh^T via f16 mma, 3 passes of 64 ch
    for (int pass = 0; pass < 3; pass++) {
        float cc[2][8][4];
        #pragma unroll
        for (int mtl = 0; mtl < 2; mtl++)
            #pragma unroll
            for (int nt = 0; nt < 8; nt++)
                #pragma unroll
                for (int j = 0; j < 4; j++) cc[mtl][nt][j] = 0.f;

        #pragma unroll
        for (int ks = 0; ks < 4; ks++) {
            const int k0 = ks * 16;
            uint32_t a[2][4];
            #pragma unroll
            for (int mtl = 0; mtl < 2; mtl++) {
                int r0 = (warp * 2 + mtl) * 16 + gID;
                const __half* g0 = gbuf + r0 * 72 + k0 + tig * 2;
                a[mtl][0] = *(const uint32_t*)(g0);
                a[mtl][1] = *(const uint32_t*)(g0 + 8 * 72);
                a[mtl][2] = *(const uint32_t*)(g0 + 8);
                a[mtl][3] = *(const uint32_t*)(g0 + 8 * 72 + 8);
            }
            #pragma unroll
            for (int nt = 0; nt < 8; nt++) {
                const __half* w0 = wuh + (pass * 64 + nt * 8 + gID) * 72 + k0 + tig * 2;
                uint32_t b0 = *(const uint32_t*)(w0);
                uint32_t b1 = *(const uint32_t*)(w0 + 8);
                mma16h(cc[0][nt], a[0][0], a[0][1], a[0][2], a[0][3], b0, b1);
                mma16h(cc[1][nt], a[1][0], a[1][1], a[1][2], a[1][3], b0, b1);
            }
        }
        // epilogue: residual + bias, direct float2 stores
        #pragma unroll
        for (int mtl = 0; mtl < 2; mtl++) {
            #pragma unroll
            for (int hf = 0; hf < 2; hf++) {
                int m = (warp * 2 + mtl) * 16 + gID + hf * 8;
                int gy = row0 + (m & 7), gx = col0 + (m >> 3);
                size_t n = (size_t)b * HW_ + gy * W_ + gx;
                const float* xr = x + n * C_;
                float* orr = out + n * C_;
                #pragma unroll
                for (int nt = 0; nt < 8; nt++) {
                    int chn = pass * 64 + nt * 8 + tig * 2;
                    float2 xv = *(const float2*)(xr + chn);
                    float v0 = cc[mtl][nt][hf * 2 + 0] + bus[chn]     + xv.x;
                    float v1 = cc[mtl][nt][hf * 2 + 1] + bus[chn + 1] + xv.y;
                    *(float2*)(orr + chn) = make_float2(v0, v1);
                }
            }
        }
    }
}

// ============================================================================
extern "C" void kernel_launch(void* const* d_in, const int* in_sizes, int n_in,
                              void* d_out, int out_size)
{
    const float* x  = (const float*)d_in[0];
    const float* W1 = (const float*)d_in[1];
    const float* b1 = (const float*)d_in[2];
    const float* W2 = (const float*)d_in[3];
    const float* b2 = (const float*)d_in[4];
    const float* mt = (const float*)d_in[5];
    const float* Wh = (const float*)d_in[6];
    const float* bh = (const float*)d_in[7];
    const float* Wd = (const float*)d_in[8];
    const float* bd = (const float*)d_in[9];
    const float* Wu = (const float*)d_in[10];
    const float* bu = (const float*)d_in[11];
    float* out = (float*)d_out;

    cudaFuncSetAttribute(k5, cudaFuncAttributeMaxDynamicSharedMemorySize, 64512);

    k0<<<1, 256>>>();
    k1<<<dim3(25, 32), 256, 44544>>>(x, W1, b1, W2, b2, mt, Wd, bd);
    k3a<<<dim3(8, 32), 256>>>();
    k4<<<144, 256, 41472>>>(Wh, bh);
    k5<<<dim3(14, 32), 256, 64512>>>(x, Wu, bu, out);
}

// round 16
// speedup vs baseline: 1.6071x; 1.0059x over previous
#include <cuda_runtime.h>
#include <cuda_fp16.h>
#include <math.h>
#include <stdint.h>

#define B_  32
#define H_  56
#define W_  56
#define C_  192
#define D_  64
#define M_  8
#define HW_ 3136
#define N_  (B_*HW_)

// ---------------- device scratch (no allocations allowed) ----------------
__device__ __half g_pf[(size_t)N_ * 64];            // [n][64] half
__device__ __half g_xp[(size_t)B_ * D_ * HW_];      // [b][d][hw] half
__device__ float  g_logits[(size_t)M_ * B_ * HW_];  // [m][b][hw]
__device__ float  g_sums[M_ * B_];                  // per (m,b): sum of exp
__device__ float  g_part[B_ * 8 * 64];              // partial mwf
__device__ __half g_convwh[(size_t)B_ * 36864];     // [b][oc*576+ic*9+tap] half

__device__ __forceinline__ float qgelu(float v) {
    return v / (1.f + __expf(-1.702f * v));
}
// mma.sync m16n8k16 f16 inputs, f32 accum
__device__ __forceinline__ void mma16h(float* c, uint32_t a0, uint32_t a1,
                                       uint32_t a2, uint32_t a3,
                                       uint32_t b0, uint32_t b1) {
    asm volatile(
        "mma.sync.aligned.m16n8k16.row.col.f32.f16.f16.f32 "
        "{%0,%1,%2,%3}, {%4,%5,%6,%7}, {%8,%9}, {%0,%1,%2,%3};"
        : "+f"(c[0]), "+f"(c[1]), "+f"(c[2]), "+f"(c[3])
        : "r"(a0), "r"(a1), "r"(a2), "r"(a3), "r"(b0), "r"(b1));
}

// ============================================================================
// K0: zero the exp-sum accumulators
// ============================================================================
__global__ void k0()
{
    g_sums[threadIdx.x] = 0.f;
}

// ============================================================================
// K1: main GEMM (f16 mma, x prefetch) -> relu/gelu; pf = hs@W2^T (f16 mma);
//     logits = pf@mask^T (f16 mma) + exp-sum atomics. 256 threads, 2 blk/SM.
// ============================================================================
__global__ __launch_bounds__(256, 2) void k1(
    const float* __restrict__ x, const float* __restrict__ W1, const float* __restrict__ b1,
    const float* __restrict__ W2, const float* __restrict__ b2, const float* __restrict__ mtok,
    const float* __restrict__ Wd, const float* __restrict__ bd)
{
    extern __shared__ __align__(16) char smraw[];
    __half* Ah  = (__half*)smraw;            // [128][40]
    __half* Bh  = (__half*)smraw + 5120;     // [128][40]
    __half* hs  = (__half*)smraw;            // overlay: [128][72]
    __half* xsh = (__half*)smraw + 9216;     // [64][132]
    __half* W2s = (__half*)smraw + 17664;    // [64][72]
    __shared__ __half mt_s[M_ * 72];
    __shared__ float es[M_];

    const int tid   = threadIdx.x;
    const int warp  = tid >> 5, lane = tid & 31;
    const int gID   = lane >> 2, tig = lane & 3;
    const int b     = blockIdx.y;
    const int hw0   = blockIdx.x * 128;
    const int P     = min(128, HW_ - hw0);

    for (int i = tid; i < 512; i += 256) {
        int m = i >> 6, k = i & 63;
        mt_s[m * 72 + k] = __float2half_rn(mtok[m * 64 + k]);
    }
    if (tid < M_) es[tid] = 0.f;

    float c[16][4];
    #pragma unroll
    for (int nt = 0; nt < 16; nt++)
        #pragma unroll
        for (int j = 0; j < 4; j++) c[nt][j] = 0.f;

    const float* xb = x + (size_t)(b * HW_ + hw0) * C_;

    float4 pre[4];
    #pragma unroll
    for (int q = 0; q < 4; q++) {
        int i = tid + q * 256;
        int r = i >> 3, qq = i & 7;
        pre[q] = (r < P) ? *(const float4*)(xb + (size_t)r * C_ + qq * 4)
                         : make_float4(0.f, 0.f, 0.f, 0.f);
    }

    for (int ch = 0; ch < 6; ch++) {
        const int k0 = ch * 32;
        __syncthreads();
        #pragma unroll
        for (int q = 0; q < 4; q++) {
            int i = tid + q * 256;
            int r = i >> 3, qq = i & 7;
            float4 v = pre[q];
            __half2* dst = (__half2*)(Ah + r * 40 + qq * 4);
            dst[0] = __floats2half2_rn(v.x, v.y);
            dst[1] = __floats2half2_rn(v.z, v.w);
        }
        for (int i = tid; i < 1024; i += 256) {
            int n = i >> 3, q = i & 7;
            const float* src = (n < 64) ? (W1 + n * C_) : (Wd + (n - 64) * C_);
            float4 v = *(const float4*)(src + k0 + q * 4);
            __half2* dst = (__half2*)(Bh + n * 40 + q * 4);
            dst[0] = __floats2half2_rn(v.x, v.y);
            dst[1] = __floats2half2_rn(v.z, v.w);
        }
        if (ch < 5) {
            const int k1n = k0 + 32;
            #pragma unroll
            for (int q = 0; q < 4; q++) {
                int i = tid + q * 256;
                int r = i >> 3, qq = i & 7;
                pre[q] = (r < P) ? *(const float4*)(xb + (size_t)r * C_ + k1n + qq * 4)
                                 : make_float4(0.f, 0.f, 0.f, 0.f);
            }
        }
        __syncthreads();

        const int arow = warp * 16 + gID;
        #pragma unroll
        for (int ks = 0; ks < 2; ks++) {
            const int kk = ks * 16;
            const __half* ap = Ah + arow * 40 + kk + 2 * tig;
            uint32_t a0 = *(const uint32_t*)(ap);
            uint32_t a1 = *(const uint32_t*)(ap + 8 * 40);
            uint32_t a2 = *(const uint32_t*)(ap + 8);
            uint32_t a3 = *(const uint32_t*)(ap + 8 * 40 + 8);
            #pragma unroll
            for (int nt = 0; nt < 16; nt++) {
                const __half* bp = Bh + (nt * 8 + gID) * 40 + kk + 2 * tig;
                uint32_t b0 = *(const uint32_t*)(bp);
                uint32_t b1 = *(const uint32_t*)(bp + 8);
                mma16h(c[nt], a0, a1, a2, a3, b0, b1);
            }
        }
    }
    __syncthreads();

    {
        const int p0 = warp * 16 + gID, p1 = p0 + 8;
        #pragma unroll
        for (int nt = 0; nt < 16; nt++) {
            const int n = nt * 8 + tig * 2;
            if (nt < 8) {
                float bia = b1[n], bib = b1[n + 1];
                *(__half2*)(hs + p0 * 72 + n) =
                    __floats2half2_rn(fmaxf(c[nt][0] + bia, 0.f), fmaxf(c[nt][1] + bib, 0.f));
                *(__half2*)(hs + p1 * 72 + n) =
                    __floats2half2_rn(fmaxf(c[nt][2] + bia, 0.f), fmaxf(c[nt][3] + bib, 0.f));
            } else {
                const int d = n - 64;
                float bia = bd[d], bib = bd[d + 1];
                xsh[d * 132 + p0]       = __float2half_rn(qgelu(c[nt][0] + bia));
                xsh[(d + 1) * 132 + p0] = __float2half_rn(qgelu(c[nt][1] + bib));
                xsh[d * 132 + p1]       = __float2half_rn(qgelu(c[nt][2] + bia));
                xsh[(d + 1) * 132 + p1] = __float2half_rn(qgelu(c[nt][3] + bib));
            }
        }
    }
    for (int i = tid; i < 4096; i += 256) {
        int o = i >> 6, kk = i & 63;
        W2s[o * 72 + kk] = __float2half_rn(W2[i]);
    }
    __syncthreads();

    {
        __half2* xpb = (__half2*)(g_xp + (size_t)b * D_ * HW_ + hw0);
        for (int i = tid; i < 4096; i += 256) {
            int d = i >> 6, pp = i & 63;
            int p = pp * 2;
            if (p < P) {
                __half2 v = __halves2half2(xsh[d * 132 + p], xsh[d * 132 + p + 1]);
                xpb[(size_t)d * (HW_ / 2) + pp] = v;
            }
        }
    }

    // pf = hs @ W2^T via f16 mma
    float cc[8][4];
    #pragma unroll
    for (int nt = 0; nt < 8; nt++)
        #pragma unroll
        for (int j = 0; j < 4; j++) cc[nt][j] = 0.f;
    {
        const int arow = warp * 16 + gID;
        #pragma unroll
        for (int ks = 0; ks < 4; ks++) {
            const int kk = ks * 16;
            const __half* ap = hs + arow * 72 + kk + 2 * tig;
            uint32_t a0 = *(const uint32_t*)(ap);
            uint32_t a1 = *(const uint32_t*)(ap + 8 * 72);
            uint32_t a2 = *(const uint32_t*)(ap + 8);
            uint32_t a3 = *(const uint32_t*)(ap + 8 * 72 + 8);
            #pragma unroll
            for (int nt = 0; nt < 8; nt++) {
                const __half* bp = W2s + (nt * 8 + gID) * 72 + kk + 2 * tig;
                uint32_t b0 = *(const uint32_t*)(bp);
                uint32_t b1 = *(const uint32_t*)(bp + 8);
                mma16h(cc[nt], a0, a1, a2, a3, b0, b1);
            }
        }
    }
    __syncthreads();

    // write pf: hs (half) + g_pf (half2)
    {
        const int p0 = warp * 16 + gID, p1 = p0 + 8;
        #pragma unroll
        for (int nt = 0; nt < 8; nt++) {
            const int n = nt * 8 + tig * 2;
            float bia = b2[n], bib = b2[n + 1];
            float v00 = cc[nt][0] + bia, v01 = cc[nt][1] + bib;
            float v10 = cc[nt][2] + bia, v11 = cc[nt][3] + bib;
            __half2 h0 = __floats2half2_rn(v00, v01);
            __half2 h1 = __floats2half2_rn(v10, v11);
            *(__half2*)(hs + p0 * 72 + n) = h0;
            *(__half2*)(hs + p1 * 72 + n) = h1;
            if (p0 < P)
                *(__half2*)(g_pf + (size_t)(b * HW_ + hw0 + p0) * 64 + n) = h0;
            if (p1 < P)
                *(__half2*)(g_pf + (size_t)(b * HW_ + hw0 + p1) * 64 + n) = h1;
        }
    }
    __syncthreads();

    // logits = pf @ mask^T via f16 mma + exp-sum accumulation
    {
        float cl[4] = {0.f, 0.f, 0.f, 0.f};
        const int arow = warp * 16 + gID;
        #pragma unroll
        for (int ks = 0; ks < 4; ks++) {
            const int kk = ks * 16;
            const __half* ap = hs + arow * 72 + kk + 2 * tig;
            uint32_t a0 = *(const uint32_t*)(ap);
            uint32_t a1 = *(const uint32_t*)(ap + 8 * 72);
            uint32_t a2 = *(const uint32_t*)(ap + 8);
            uint32_t a3 = *(const uint32_t*)(ap + 8 * 72 + 8);
            const __half* bp = mt_s + gID * 72 + kk + 2 * tig;
            uint32_t b0 = *(const uint32_t*)(bp);
            uint32_t b1 = *(const uint32_t*)(bp + 8);
            mma16h(cl, a0, a1, a2, a3, b0, b1);
        }
        const int p0 = warp * 16 + gID, p1 = p0 + 8;
        const int m0 = tig * 2, m1 = tig * 2 + 1;
        float e0 = 0.f, e1 = 0.f;
        if (p0 < P) {
            g_logits[(size_t)(m0 * B_ + b) * HW_ + hw0 + p0] = cl[0];
            g_logits[(size_t)(m1 * B_ + b) * HW_ + hw0 + p0] = cl[1];
            e0 += __expf(cl[0]); e1 += __expf(cl[1]);
        }
        if (p1 < P) {
            g_logits[(size_t)(m0 * B_ + b) * HW_ + hw0 + p1] = cl[2];
            g_logits[(size_t)(m1 * B_ + b) * HW_ + hw0 + p1] = cl[3];
            e0 += __expf(cl[2]); e1 += __expf(cl[3]);
        }
        atomicAdd(&es[m0], e0);
        atomicAdd(&es[m1], e1);
        __syncthreads();
        if (tid < M_) atomicAdd(&g_sums[tid * B_ + b], es[tid]);
    }
}

// ============================================================================
// K3a: partial mwf over 392-position chunks. grid (8, 32). pf half.
// ============================================================================
__global__ __launch_bounds__(256) void k3a()
{
    const int chunk = blockIdx.x, b = blockIdx.y;
    const int tid = threadIdx.x;
    const int p0 = chunk * 392;
    __shared__ float ms[392];
    __shared__ float izs[M_];
    __shared__ float red[4][64];

    if (tid < M_) izs[tid] = 1.f / g_sums[tid * B_ + b];
    __syncthreads();

    for (int p = tid; p < 392; p += 256) {
        float s = 0.f;
        #pragma unroll
        for (int m = 0; m < M_; m++)
            s += __expf(g_logits[(size_t)(m * B_ + b) * HW_ + p0 + p]) * izs[m];
        ms[p] = s;
    }
    __syncthreads();

    int k = tid & 63, g = tid >> 6;
    float acc = 0.f;
    const __half* pfb = g_pf + (size_t)(b * HW_ + p0) * 64;
    for (int p = g; p < 392; p += 4)
        acc = fmaf(ms[p], __half2float(pfb[(size_t)p * 64 + k]), acc);
    red[g][k] = acc;
    __syncthreads();
    if (g == 0)
        g_part[(b * 8 + chunk) * 64 + k] = red[0][k] + red[1][k] + red[2][k] + red[3][k];
}

// ============================================================================
// K4: reduce g_part -> mwf (half smem); conv_w = Wh @ mwf^T via f16 mma.
// 288 blocks x 128 o-rows (2 blocks/SM for latency hiding), coalesced output.
// ============================================================================
__global__ __launch_bounds__(256, 2) void k4(const float* __restrict__ Wh,
                                             const float* __restrict__ bh)
{
    extern __shared__ __align__(16) char smraw[];
    __half* mwh = (__half*)smraw;            // [32][72]  (4608 B)
    __half* whs = (__half*)smraw + 2304;     // [128][72] (18432 B)
    __half* cs  = (__half*)smraw + 2304;     // overlay after mma: [128][34]

    const int tid  = threadIdx.x;
    const int warp = tid >> 5, lane = tid & 31;
    const int gID  = lane >> 2, tig = lane & 3;
    const int o0   = blockIdx.x * 128;

    for (int i = tid; i < 2048; i += 256) {
        int bb = i >> 6, k = i & 63;
        float acc = 0.f;
        #pragma unroll
        for (int cch = 0; cch < 8; cch++) acc += g_part[(bb * 8 + cch) * 64 + k];
        mwh[bb * 72 + k] = __float2half_rn(acc);
    }
    for (int i = tid; i < 8192; i += 256) {
        int row = i >> 6, k = i & 63;
        whs[row * 72 + k] = __float2half_rn(Wh[(size_t)(o0 + row) * 64 + k]);
    }
    __syncthreads();

    // mma: M=128 (warp owns 1 m-tile), N=32, K=64
    float cc[4][4];
    #pragma unroll
    for (int nt = 0; nt < 4; nt++)
        #pragma unroll
        for (int j = 0; j < 4; j++) cc[nt][j] = 0.f;

    #pragma unroll
    for (int ks = 0; ks < 4; ks++) {
        const int kk = ks * 16;
        const __half* ap = whs + (warp * 16 + gID) * 72 + kk + 2 * tig;
        uint32_t a0 = *(const uint32_t*)(ap);
        uint32_t a1 = *(const uint32_t*)(ap + 8 * 72);
        uint32_t a2 = *(const uint32_t*)(ap + 8);
        uint32_t a3 = *(const uint32_t*)(ap + 8 * 72 + 8);
        #pragma unroll
        for (int nt = 0; nt < 4; nt++) {
            const __half* bp = mwh + (nt * 8 + gID) * 72 + kk + 2 * tig;
            uint32_t b0 = *(const uint32_t*)(bp);
            uint32_t b1 = *(const uint32_t*)(bp + 8);
            mma16h(cc[nt], a0, a1, a2, a3, b0, b1);
        }
    }
    __syncthreads();

    // bias + transpose to cs[o_local][b]
    {
        int r0 = warp * 16 + gID;
        float bia0 = bh[o0 + r0], bia1 = bh[o0 + r0 + 8];
        #pragma unroll
        for (int nt = 0; nt < 4; nt++) {
            int col = nt * 8 + tig * 2;
            cs[r0 * 34 + col]           = __float2half_rn(cc[nt][0] + bia0);
            cs[r0 * 34 + col + 1]       = __float2half_rn(cc[nt][1] + bia0);
            cs[(r0 + 8) * 34 + col]     = __float2half_rn(cc[nt][2] + bia1);
            cs[(r0 + 8) * 34 + col + 1] = __float2half_rn(cc[nt][3] + bia1);
        }
    }
    __syncthreads();

    for (int i = tid; i < 4096; i += 256) {
        int b = i >> 7, ol = i & 127;
        g_convwh[(size_t)b * 36864 + o0 + ol] = cs[ol * 34 + b];
    }
}

// ============================================================================
// K5: conv (f16 m16n8k16 mma) + quickGELU + up-proj (f16 mma) + residual.
// ============================================================================
__global__ __launch_bounds__(256, 2) void k5(const float* __restrict__ x,
                                             const float* __restrict__ Wu,
                                             const float* __restrict__ bu,
                                             float* __restrict__ out)
{
    extern __shared__ float sm[];
    __half* hbase = (__half*)sm;
    __half* hin_h = hbase;             // [340 spatial][20]
    __half* Bw_h  = hbase + 6800;      // [576][24]
    __half* gbuf  = hbase;             // overlay: [256 m][72]
    __half* wuh   = hbase + 18432;     // overlay: [192 n][72]
    __shared__ float bus[C_];

    const int tid  = threadIdx.x;
    const int warp = tid >> 5, lane = tid & 31;
    const int gID  = lane >> 2, tig = lane & 3;
    const int b    = blockIdx.y;
    const int t    = blockIdx.x;
    const int row0 = (t % 7) * 8;
    const int col0 = (t / 7) * 24;

    for (int i = tid; i < C_; i += 256) bus[i] = bu[i];

    float c[2][8][4];
    #pragma unroll
    for (int mtl = 0; mtl < 2; mtl++)
        #pragma unroll
        for (int nt = 0; nt < 8; nt++)
            #pragma unroll
            for (int j = 0; j < 4; j++) c[mtl][nt][j] = 0.f;

    for (int ci = 0; ci < 4; ci++) {
        __syncthreads();
        for (int i = tid; i < 2720; i += 256) {
            int s = i >> 3, jc = i & 7;
            int hr = s / 34, hc = s % 34;
            int gy = row0 - 1 + hr, gx = col0 - 1 + hc;
            __half2 v = __halves2half2(__float2half(0.f), __float2half(0.f));
            if (gy >= 0 && gy < H_ && gx >= 0 && gx < W_) {
                size_t base = (size_t)(b * D_ + ci * 16 + 2 * jc) * HW_ + gy * W_ + gx;
                v = __halves2half2(g_xp[base], g_xp[base + HW_]);
            }
            *(__half2*)(hin_h + s * 20 + 2 * jc) = v;
        }
        for (int i = tid; i < 9216; i += 256) {
            int ic = i & 15, rest = i >> 4;
            int oc = rest & 63, tap = rest >> 6;
            Bw_h[rest * 24 + ic] =
                g_convwh[(size_t)b * 36864 + oc * 576 + (ci * 16 + ic) * 9 + tap];
        }
        __syncthreads();

        #pragma unroll
        for (int tap = 0; tap < 9; tap++) {
            const int dy = tap / 3, dx = tap % 3;
            uint32_t a[2][4];
            #pragma unroll
            for (int mtl = 0; mtl < 2; mtl++) {
                const __half* ap = hin_h +
                    ((gID + dy) * 34 + 4 * warp + 2 * mtl + dx) * 20 + 2 * tig;
                a[mtl][0] = *(const uint32_t*)(ap);
                a[mtl][1] = *(const uint32_t*)(ap + 20);
                a[mtl][2] = *(const uint32_t*)(ap + 8);
                a[mtl][3] = *(const uint32_t*)(ap + 28);
            }
            #pragma unroll
            for (int nt = 0; nt < 8; nt++) {
                const __half* bp = Bw_h + (tap * 64 + nt * 8 + gID) * 24 + 2 * tig;
                uint32_t b0 = *(const uint32_t*)(bp);
                uint32_t b1 = *(const uint32_t*)(bp + 8);
                mma16h(c[0][nt], a[0][0], a[0][1], a[0][2], a[0][3], b0, b1);
                mma16h(c[1][nt], a[1][0], a[1][1], a[1][2], a[1][3], b0, b1);
            }
        }
    }
    __syncthreads();

    #pragma unroll
    for (int mtl = 0; mtl < 2; mtl++) {
        int m0 = (2 * warp + mtl) * 16 + gID;
        #pragma unroll
        for (int nt = 0; nt < 8; nt++) {
            int oc = nt * 8 + tig * 2;
            *(__half2*)(gbuf + m0 * 72 + oc) =
                __floats2half2_rn(qgelu(c[mtl][nt][0]), qgelu(c[mtl][nt][1]));
            *(__half2*)(gbuf + (m0 + 8) * 72 + oc) =
                __floats2half2_rn(qgelu(c[mtl][nt][2]), qgelu(c[mtl][nt][3]));
        }
    }
    for (int i = tid; i < 12288; i += 256) {
        int n = i >> 6, k = i & 63;
        wuh[n * 72 + k] = __float2half_rn(Wu[i]);
    }
    __syncthreads();

    for (int pass = 0; pass < 3; pass++) {
        float cc[2][8][4];
        #pragma unroll
        for (int mtl = 0; mtl < 2; mtl++)
            #pragma unroll
            for (int nt = 0; nt < 8; nt++)
                #pragma unroll
                for (int j = 0; j < 4; j++) cc[mtl][nt][j] = 0.f;

        #pragma unroll
        for (int ks = 0; ks < 4; ks++) {
            const int k0 = ks * 16;
            uint32_t a[2][4];
            #pragma unroll
            for (int mtl = 0; mtl < 2; mtl++) {
                int r0 = (warp * 2 + mtl) * 16 + gID;
                const __half* g0 = gbuf + r0 * 72 + k0 + tig * 2;
                a[mtl][0] = *(const uint32_t*)(g0);
                a[mtl][1] = *(const uint32_t*)(g0 + 8 * 72);
                a[mtl][2] = *(const uint32_t*)(g0 + 8);
                a[mtl][3] = *(const uint32_t*)(g0 + 8 * 72 + 8);
            }
            #pragma unroll
            for (int nt = 0; nt < 8; nt++) {
                const __half* w0 = wuh + (pass * 64 + nt * 8 + gID) * 72 + k0 + tig * 2;
                uint32_t b0 = *(const uint32_t*)(w0);
                uint32_t b1 = *(const uint32_t*)(w0 + 8);
                mma16h(cc[0][nt], a[0][0], a[0][1], a[0][2], a[0][3], b0, b1);
                mma16h(cc[1][nt], a[1][0], a[1][1], a[1][2], a[1][3], b0, b1);
            }
        }
        #pragma unroll
        for (int mtl = 0; mtl < 2; mtl++) {
            #pragma unroll
            for (int hf = 0; hf < 2; hf++) {
                int m = (warp * 2 + mtl) * 16 + gID + hf * 8;
                int gy = row0 + (m & 7), gx = col0 + (m >> 3);
                size_t n = (size_t)b * HW_ + gy * W_ + gx;
                const float* xr = x + n * C_;
                float* orr = out + n * C_;
                #pragma unroll
                for (int nt = 0; nt < 8; nt++) {
                    int chn = pass * 64 + nt * 8 + tig * 2;
                    float2 xv = *(const float2*)(xr + chn);
                    float v0 = cc[mtl][nt][hf * 2 + 0] + bus[chn]     + xv.x;
                    float v1 = cc[mtl][nt][hf * 2 + 1] + bus[chn + 1] + xv.y;
                    *(float2*)(orr + chn) = make_float2(v0, v1);
                }
            }
        }
    }
}

// ============================================================================
extern "C" void kernel_launch(void* const* d_in, const int* in_sizes, int n_in,
                              void* d_out, int out_size)
{
    const float* x  = (const float*)d_in[0];
    const float* W1 = (const float*)d_in[1];
    const float* b1 = (const float*)d_in[2];
    const float* W2 = (const float*)d_in[3];
    const float* b2 = (const float*)d_in[4];
    const float* mt = (const float*)d_in[5];
    const float* Wh = (const float*)d_in[6];
    const float* bh = (const float*)d_in[7];
    const float* Wd = (const float*)d_in[8];
    const float* bd = (const float*)d_in[9];
    const float* Wu = (const float*)d_in[10];
    const float* bu = (const float*)d_in[11];
    float* out = (float*)d_out;

    cudaFuncSetAttribute(k5, cudaFuncAttributeMaxDynamicSharedMemorySize, 64512);

    k0<<<1, 256>>>();
    k1<<<dim3(25, 32), 256, 44544>>>(x, W1, b1, W2, b2, mt, Wd, bd);
    k3a<<<dim3(8, 32), 256>>>();
    k4<<<288, 256, 23040>>>(Wh, bh);
    k5<<<dim3(14, 32), 256, 64512>>>(x, Wu, bu, out);
}